// round 4
// baseline (speedup 1.0000x reference)
#include <cuda_runtime.h>
#include <math.h>

#define B_ 2
#define S_ 2048
#define D_ 1024
#define H_ 16
#define HD_ 64
#define NEGINF (-9000000000000000.0f)
// logits scale folded with log2(e): softmax computed in base-2 domain
#define SCALE2 0.1803368801111204f

// Scratch (device globals: allocation-free rule)
__device__ float g_Q[B_ * H_ * S_ * HD_];
__device__ float g_K[B_ * H_ * S_ * HD_];
__device__ float g_V[B_ * H_ * S_ * HD_];
__device__ float g_C[B_ * S_ * D_];
__device__ float g_X[B_ * S_ * D_];        // tf32-rounded x
__device__ float g_W1[3 * D_ * D_];        // tf32-rounded w_qkv
__device__ float g_W2[D_ * D_];            // tf32-rounded w_o
__device__ unsigned g_Mb[S_ * (S_ / 32)];  // bit-packed mask

__device__ __forceinline__ unsigned f2tf(float x) {
    unsigned r;
    asm("cvt.rna.tf32.f32 %0, %1;" : "=r"(r) : "f"(x));
    return r;
}
__device__ __forceinline__ float ex2(float x) {
    float y;
    asm("ex2.approx.f32 %0, %1;" : "=f"(y) : "f"(x));
    return y;
}
__device__ __forceinline__ void mma_tf32(float c[4], unsigned a0, unsigned a1,
                                         unsigned a2, unsigned a3,
                                         unsigned b0, unsigned b1) {
    asm volatile(
        "mma.sync.aligned.m16n8k8.row.col.f32.tf32.tf32.f32 "
        "{%0,%1,%2,%3}, {%4,%5,%6,%7}, {%8,%9}, {%0,%1,%2,%3};"
        : "+f"(c[0]), "+f"(c[1]), "+f"(c[2]), "+f"(c[3])
        : "r"(a0), "r"(a1), "r"(a2), "r"(a3), "r"(b0), "r"(b1));
}
__device__ __forceinline__ void cp16(unsigned dst, const void* src) {
    asm volatile("cp.async.cg.shared.global [%0], [%1], 16;" ::"r"(dst), "l"(src));
}
#define CP_COMMIT() asm volatile("cp.async.commit_group;" ::: "memory")
template <int N>
__device__ __forceinline__ void cp_wait() {
    asm volatile("cp.async.wait_group %0;" ::"n"(N) : "memory");
}
__device__ __forceinline__ unsigned smem_u32(const void* p) {
    return (unsigned)__cvta_generic_to_shared(p);
}

// ---------------------------------------------------------------------------
__global__ __launch_bounds__(256) void maskpack(const int* __restrict__ mask) {
    int idx = blockIdx.x * 256 + threadIdx.x;
    int r = idx >> 6, wc = idx & 63;
    const int4* p = (const int4*)(mask + (size_t)r * S_ + wc * 32);
    unsigned bits = 0;
#pragma unroll
    for (int i = 0; i < 8; ++i) {
        int4 m = __ldg(p + i);
        bits |= (unsigned)(m.x != 0) << (4 * i)
              | (unsigned)(m.y != 0) << (4 * i + 1)
              | (unsigned)(m.z != 0) << (4 * i + 2)
              | (unsigned)(m.w != 0) << (4 * i + 3);
    }
    g_Mb[idx] = bits;
}

// Pre-round a float array to tf32 bit patterns (one-time).
__global__ __launch_bounds__(256) void conv_tf(const float* __restrict__ in,
                                               float* __restrict__ outp) {
    int i = (blockIdx.x * 256 + threadIdx.x) * 4;
    float4 v = *(const float4*)(in + i);
    uint4 o;
    o.x = f2tf(v.x); o.y = f2tf(v.y); o.z = f2tf(v.z); o.w = f2tf(v.w);
    *(uint4*)(outp + i) = o;
}

// ---------------------------------------------------------------------------
// Tensor-core GEMM, cp.async 3-stage pipeline. C[M,N] = A @ W^T + bias.
// Block 128x128, BK=32, 256 thr, warp tile 64x32. A/W are tf32-pre-rounded.
// MODE 0: scatter into g_Q/g_K/g_V (tf32-rounded). MODE 1: write out raw.
// ---------------------------------------------------------------------------
__device__ __forceinline__ void gemm_stage(const float* __restrict__ A,
                                           const float* __restrict__ W,
                                           int m0, int n0, int kk,
                                           unsigned sA, unsigned sB, int t) {
    const int lr = t >> 3, lc = t & 7;
    const int ko = kk * 32;
#pragma unroll
    for (int i = 0; i < 4; ++i) {
        int row = lr + i * 32;
        cp16(sA + (unsigned)(row * 36 + lc * 4) * 4,
             A + (size_t)(m0 + row) * D_ + ko + lc * 4);
        cp16(sB + (unsigned)(row * 36 + lc * 4) * 4,
             W + (size_t)(n0 + row) * D_ + ko + lc * 4);
    }
}

template <int MODE>
__global__ __launch_bounds__(256) void gemm_tc(const float* __restrict__ A,
                                               const float* __restrict__ W,
                                               const float* __restrict__ bias,
                                               float* __restrict__ out) {
    extern __shared__ unsigned sh[];
    unsigned* As = sh;                  // [3][128*36]
    unsigned* Bs = sh + 3 * 128 * 36;   // [3][128*36]

    const int m0 = blockIdx.y * 128;
    const int n0 = blockIdx.x * 128;
    const int t = threadIdx.x;
    const int w = t >> 5;
    const int lane = t & 31;
    const int g = lane >> 2;
    const int t4 = lane & 3;
    const int wm = (w >> 2) * 64;
    const int wn = (w & 3) * 32;

    const float* Aptr = (MODE == 1 ? g_C : A);
    const unsigned sA0 = smem_u32(As);
    const unsigned sB0 = smem_u32(Bs);
    const unsigned bufB = 128 * 36 * 4;  // bytes per buffer

    gemm_stage(Aptr, W, m0, n0, 0, sA0, sB0, t);
    CP_COMMIT();
    gemm_stage(Aptr, W, m0, n0, 1, sA0 + bufB, sB0 + bufB, t);
    CP_COMMIT();

    float acc[4][4][4];
#pragma unroll
    for (int mt = 0; mt < 4; ++mt)
#pragma unroll
        for (int nt = 0; nt < 4; ++nt)
#pragma unroll
            for (int i = 0; i < 4; ++i) acc[mt][nt][i] = 0.0f;

    int cur = 0;
    for (int k0 = 0; k0 < 32; ++k0) {
        cp_wait<1>();
        __syncthreads();
        if (k0 + 2 < 32) {
            int nb = cur + 2;
            if (nb >= 3) nb -= 3;
            gemm_stage(Aptr, W, m0, n0, k0 + 2, sA0 + nb * bufB, sB0 + nb * bufB, t);
        }
        CP_COMMIT();

        const unsigned* Ab = As + cur * 128 * 36;
        const unsigned* Bb = Bs + cur * 128 * 36;
#pragma unroll
        for (int ks = 0; ks < 4; ++ks) {
            unsigned a[4][4];
#pragma unroll
            for (int mt = 0; mt < 4; ++mt) {
                const unsigned* q = &Ab[(wm + mt * 16) * 36 + ks * 8];
                a[mt][0] = q[g * 36 + t4];
                a[mt][1] = q[(g + 8) * 36 + t4];
                a[mt][2] = q[g * 36 + t4 + 4];
                a[mt][3] = q[(g + 8) * 36 + t4 + 4];
            }
#pragma unroll
            for (int nt = 0; nt < 4; ++nt) {
                unsigned b0 = Bb[(wn + nt * 8 + g) * 36 + ks * 8 + t4];
                unsigned b1 = Bb[(wn + nt * 8 + g) * 36 + ks * 8 + t4 + 4];
#pragma unroll
                for (int mt = 0; mt < 4; ++mt)
                    mma_tf32(acc[mt][nt], a[mt][0], a[mt][1], a[mt][2], a[mt][3], b0, b1);
            }
        }
        cur = (cur == 2) ? 0 : cur + 1;
    }

    // epilogue
#pragma unroll
    for (int mt = 0; mt < 4; ++mt) {
#pragma unroll
        for (int nt = 0; nt < 4; ++nt) {
            int ncol = n0 + wn + nt * 8 + 2 * t4;
            float bx = __ldg(&bias[ncol]);
            float by = __ldg(&bias[ncol + 1]);
#pragma unroll
            for (int rr = 0; rr < 2; ++rr) {
                int m = m0 + wm + mt * 16 + g + rr * 8;
                float vx = acc[mt][nt][rr * 2] + bx;
                float vy = acc[mt][nt][rr * 2 + 1] + by;
                if (MODE == 0) {
                    int bb = m >> 11, ss = m & 2047;
                    int h = ncol / 192;
                    int rem = ncol - h * 192;
                    int part = rem >> 6;
                    int d = rem & 63;
                    size_t dst = (((size_t)(bb * H_ + h)) * S_ + ss) * HD_ + d;
                    float* dstp = (part == 0 ? g_Q : (part == 1 ? g_K : g_V));
                    dstp[dst] = __uint_as_float(f2tf(vx));       // pre-round for attn
                    dstp[dst + 1] = __uint_as_float(f2tf(vy));
                } else {
                    *(float2*)&out[(size_t)m * D_ + ncol] = make_float2(vx, vy);
                }
            }
        }
    }
}

// ---------------------------------------------------------------------------
// Flash attention, tf32 mma, cp.async double-buffered K/V (issue-ahead-1).
// grid=(S/128, B*H), 256 thr. Warp owns 16 q-rows; softmax stats in regs.
// Q/K/V pre-rounded to tf32 by gemm0's epilogue -> raw async copies.
// ---------------------------------------------------------------------------
__device__ __forceinline__ void attn_stage(unsigned sK, unsigned sV,
                                           const float* __restrict__ Kt,
                                           const float* __restrict__ Vt, int t) {
    const int r = t >> 4, seg = t & 15;
#pragma unroll
    for (int i = 0; i < 4; ++i) {
        int row = r + i * 16;
        cp16(sK + (unsigned)(row * 68 + seg * 4) * 4, Kt + (size_t)row * HD_ + seg * 4);
        cp16(sV + (unsigned)(row * 72 + seg * 4) * 4, Vt + (size_t)row * HD_ + seg * 4);
    }
}

__global__ __launch_bounds__(256, 2) void attn_tc() {
    extern __shared__ unsigned sh[];
    unsigned* Qs = sh;                        // [128][68]
    unsigned* Ks = sh + 128 * 68;             // [2][64][68]
    unsigned* Vs = Ks + 2 * 64 * 68;          // [2][64][72]

    const int bh = blockIdx.y;
    const int q0 = blockIdx.x * 128;
    const int t = threadIdx.x;
    const int w = t >> 5;
    const int lane = t & 31;
    const int g = lane >> 2;
    const int t4 = lane & 3;

    const size_t base = (size_t)bh * (S_ * HD_);
    const float* Qg = g_Q + base;
    const float* Kg = g_K + base;
    const float* Vg = g_V + base;

    const unsigned sQ = smem_u32(Qs);
    const unsigned sK0 = smem_u32(Ks);
    const unsigned sV0 = smem_u32(Vs);
    const unsigned kBuf = 64 * 68 * 4, vBuf = 64 * 72 * 4;

    // prologue: Q + K/V tile 0, one group
#pragma unroll
    for (int i = 0; i < 8; ++i) {
        int idx = t + i * 256;
        int row = idx >> 4, seg = idx & 15;
        cp16(sQ + (unsigned)(row * 68 + seg * 4) * 4,
             Qg + (size_t)(q0 + row) * HD_ + seg * 4);
    }
    attn_stage(sK0, sV0, Kg, Vg, t);
    CP_COMMIT();

    const int qrow0 = q0 + w * 16 + g;
    const int qrow1 = qrow0 + 8;
    const unsigned* mbp0 = g_Mb + (size_t)qrow0 * 64;
    const unsigned* mbp1 = g_Mb + (size_t)qrow1 * 64;

    float o[8][4];
#pragma unroll
    for (int nt = 0; nt < 8; ++nt)
#pragma unroll
        for (int i = 0; i < 4; ++i) o[nt][i] = 0.0f;
    float m0s = -INFINITY, m1s = -INFINITY, l0 = 0.0f, l1 = 0.0f;

    for (int j = 0; j < 32; ++j) {
        cp_wait<0>();
        __syncthreads();
        if (j < 31) {
            int nb = (j + 1) & 1;
            attn_stage(sK0 + nb * kBuf, sV0 + nb * vBuf,
                       Kg + (size_t)(j + 1) * 64 * HD_,
                       Vg + (size_t)(j + 1) * 64 * HD_, t);
        }
        CP_COMMIT();

        const int kbK = (j & 1) * 64 * 68;
        const int kbV = (j & 1) * 64 * 72;
        uint2 mb0 = *(const uint2*)(mbp0 + j * 2);
        uint2 mb1 = *(const uint2*)(mbp1 + j * 2);

        // S = Q @ K^T
        float sc[8][4];
#pragma unroll
        for (int nt = 0; nt < 8; ++nt)
#pragma unroll
            for (int i = 0; i < 4; ++i) sc[nt][i] = 0.0f;
#pragma unroll
        for (int ks = 0; ks < 8; ++ks) {
            const unsigned* qb = &Qs[(w * 16) * 68 + ks * 8];
            unsigned a0 = qb[g * 68 + t4];
            unsigned a1 = qb[(g + 8) * 68 + t4];
            unsigned a2 = qb[g * 68 + t4 + 4];
            unsigned a3 = qb[(g + 8) * 68 + t4 + 4];
#pragma unroll
            for (int nt = 0; nt < 8; ++nt) {
                unsigned b0 = Ks[kbK + (nt * 8 + g) * 68 + ks * 8 + t4];
                unsigned b1 = Ks[kbK + (nt * 8 + g) * 68 + ks * 8 + t4 + 4];
                mma_tf32(sc[nt], a0, a1, a2, a3, b0, b1);
            }
        }

        // scale (base-2 domain) + mask from bit matrix
#pragma unroll
        for (int nt = 0; nt < 8; ++nt) {
            unsigned w0 = (nt < 4) ? mb0.x : mb0.y;
            unsigned w1 = (nt < 4) ? mb1.x : mb1.y;
            int shv = (nt & 3) * 8 + 2 * t4;
            unsigned b0 = w0 >> shv;
            unsigned b1 = w1 >> shv;
            sc[nt][0] = (b0 & 1) ? sc[nt][0] * SCALE2 : NEGINF;
            sc[nt][1] = (b0 & 2) ? sc[nt][1] * SCALE2 : NEGINF;
            sc[nt][2] = (b1 & 1) ? sc[nt][2] * SCALE2 : NEGINF;
            sc[nt][3] = (b1 & 2) ? sc[nt][3] * SCALE2 : NEGINF;
        }

        // online softmax (register stats, base-2)
        float mx0 = -INFINITY, mx1 = -INFINITY;
#pragma unroll
        for (int nt = 0; nt < 8; ++nt) {
            mx0 = fmaxf(mx0, fmaxf(sc[nt][0], sc[nt][1]));
            mx1 = fmaxf(mx1, fmaxf(sc[nt][2], sc[nt][3]));
        }
        mx0 = fmaxf(mx0, __shfl_xor_sync(0xffffffffu, mx0, 1));
        mx0 = fmaxf(mx0, __shfl_xor_sync(0xffffffffu, mx0, 2));
        mx1 = fmaxf(mx1, __shfl_xor_sync(0xffffffffu, mx1, 1));
        mx1 = fmaxf(mx1, __shfl_xor_sync(0xffffffffu, mx1, 2));
        float mn0 = fmaxf(m0s, mx0), mn1 = fmaxf(m1s, mx1);
        float al0 = ex2(m0s - mn0), al1 = ex2(m1s - mn1);
        m0s = mn0; m1s = mn1;
        float rs0 = 0.0f, rs1 = 0.0f;
#pragma unroll
        for (int nt = 0; nt < 8; ++nt) {
            sc[nt][0] = ex2(sc[nt][0] - mn0);
            sc[nt][1] = ex2(sc[nt][1] - mn0);
            sc[nt][2] = ex2(sc[nt][2] - mn1);
            sc[nt][3] = ex2(sc[nt][3] - mn1);
            rs0 += sc[nt][0] + sc[nt][1];
            rs1 += sc[nt][2] + sc[nt][3];
        }
        rs0 += __shfl_xor_sync(0xffffffffu, rs0, 1);
        rs0 += __shfl_xor_sync(0xffffffffu, rs0, 2);
        rs1 += __shfl_xor_sync(0xffffffffu, rs1, 1);
        rs1 += __shfl_xor_sync(0xffffffffu, rs1, 2);
        l0 = al0 * l0 + rs0;
        l1 = al1 * l1 + rs1;
#pragma unroll
        for (int nt = 0; nt < 8; ++nt) {
            o[nt][0] *= al0; o[nt][1] *= al0;
            o[nt][2] *= al1; o[nt][3] *= al1;
        }

        // O += P @ V : relayout P C-frag -> A-frag via shfl
        const int s0l = (lane & ~3) | (t4 >> 1);
        const int s1l = s0l + 2;
        const bool odd = (t4 & 1);
#pragma unroll
        for (int kt = 0; kt < 8; ++kt) {
            float e00 = __shfl_sync(0xffffffffu, sc[kt][0], s0l);
            float e01 = __shfl_sync(0xffffffffu, sc[kt][1], s0l);
            float e10 = __shfl_sync(0xffffffffu, sc[kt][2], s0l);
            float e11 = __shfl_sync(0xffffffffu, sc[kt][3], s0l);
            float f00 = __shfl_sync(0xffffffffu, sc[kt][0], s1l);
            float f01 = __shfl_sync(0xffffffffu, sc[kt][1], s1l);
            float f10 = __shfl_sync(0xffffffffu, sc[kt][2], s1l);
            float f11 = __shfl_sync(0xffffffffu, sc[kt][3], s1l);
            unsigned a0 = f2tf(odd ? e01 : e00);
            unsigned a1 = f2tf(odd ? e11 : e10);
            unsigned a2 = f2tf(odd ? f01 : f00);
            unsigned a3 = f2tf(odd ? f11 : f10);
#pragma unroll
            for (int nt = 0; nt < 8; ++nt) {
                unsigned b0 = Vs[kbV + (kt * 8 + t4) * 72 + nt * 8 + g];
                unsigned b1 = Vs[kbV + (kt * 8 + t4 + 4) * 72 + nt * 8 + g];
                mma_tf32(o[nt], a0, a1, a2, a3, b0, b1);
            }
        }
    }

    // epilogue: normalize, tf32-round, write ctx [B,S,D]
    const int bb = bh >> 4;
    const int h = bh & 15;
    float inv0 = 1.0f / l0, inv1 = 1.0f / l1;
#pragma unroll
    for (int nt = 0; nt < 8; ++nt) {
        int dcol = h * 64 + nt * 8 + 2 * t4;
        size_t r0 = ((size_t)bb * S_ + qrow0) * D_ + dcol;
        size_t r1 = ((size_t)bb * S_ + qrow1) * D_ + dcol;
        float2 v0 = make_float2(__uint_as_float(f2tf(o[nt][0] * inv0)),
                                __uint_as_float(f2tf(o[nt][1] * inv0)));
        float2 v1 = make_float2(__uint_as_float(f2tf(o[nt][2] * inv1)),
                                __uint_as_float(f2tf(o[nt][3] * inv1)));
        *(float2*)&g_C[r0] = v0;
        *(float2*)&g_C[r1] = v1;
    }
}

// ---------------------------------------------------------------------------
extern "C" void kernel_launch(void* const* d_in, const int* in_sizes, int n_in,
                              void* d_out, int out_size) {
    const float* x     = (const float*)d_in[0];
    const int*   mask  = (const int*)d_in[1];
    const float* w_qkv = (const float*)d_in[2];
    const float* b_qkv = (const float*)d_in[3];
    const float* w_o   = (const float*)d_in[4];
    const float* b_o   = (const float*)d_in[5];
    float* out = (float*)d_out;

    const int gemm_smem = 6 * 128 * 36 * (int)sizeof(unsigned);  // 110592
    const int attn_smem = (128 * 68 + 2 * 64 * 68 + 2 * 64 * 72) * (int)sizeof(unsigned);

    cudaFuncSetAttribute(gemm_tc<0>, cudaFuncAttributeMaxDynamicSharedMemorySize, gemm_smem);
    cudaFuncSetAttribute(gemm_tc<1>, cudaFuncAttributeMaxDynamicSharedMemorySize, gemm_smem);
    cudaFuncSetAttribute(attn_tc, cudaFuncAttributeMaxDynamicSharedMemorySize, attn_smem);

    // 0) one-time prep: pack mask bits; pre-round inputs/weights to tf32
    maskpack<<<S_ * (S_ / 32) / 256, 256>>>(mask);
    conv_tf<<<B_ * S_ * D_ / 1024, 256>>>(x, g_X);
    conv_tf<<<3 * D_ * D_ / 1024, 256>>>(w_qkv, g_W1);
    conv_tf<<<D_ * D_ / 1024, 256>>>(w_o, g_W2);

    // 1) QKV projection
    gemm_tc<0><<<dim3(3072 / 128, 4096 / 128), 256, gemm_smem>>>(g_X, g_W1, b_qkv, nullptr);

    // 2) flash attention
    attn_tc<<<dim3(S_ / 128, B_ * H_), 256, attn_smem>>>();

    // 3) output projection
    gemm_tc<1><<<dim3(1024 / 128, 4096 / 128), 256, gemm_smem>>>(nullptr, g_W2, b_o, out);
}

// round 5
// speedup vs baseline: 1.6760x; 1.6760x over previous
#include <cuda_runtime.h>
#include <math.h>

#define B_ 2
#define S_ 2048
#define D_ 1024
#define H_ 16
#define HD_ 64
#define NEGINF (-9000000000000000.0f)
// logits scale folded with log2(e): softmax computed in base-2 domain
#define SCALE2 0.1803368801111204f

// Scratch (device globals: allocation-free rule)
__device__ float g_Q[B_ * H_ * S_ * HD_];
__device__ float g_K[B_ * H_ * S_ * HD_];
__device__ float g_V[B_ * H_ * S_ * HD_];
__device__ float g_C[B_ * S_ * D_];
__device__ float g_X[B_ * S_ * D_];        // tf32-rounded x
__device__ float g_W1[3 * D_ * D_];        // tf32-rounded w_qkv
__device__ float g_W2[D_ * D_];            // tf32-rounded w_o
__device__ unsigned g_Mb[S_ * (S_ / 32)];  // bit-packed mask

__device__ __forceinline__ unsigned f2tf(float x) {
    unsigned r;
    asm("cvt.rna.tf32.f32 %0, %1;" : "=r"(r) : "f"(x));
    return r;
}
__device__ __forceinline__ float ex2(float x) {
    float y;
    asm("ex2.approx.f32 %0, %1;" : "=f"(y) : "f"(x));
    return y;
}
__device__ __forceinline__ void mma_tf32(float c[4], unsigned a0, unsigned a1,
                                         unsigned a2, unsigned a3,
                                         unsigned b0, unsigned b1) {
    asm volatile(
        "mma.sync.aligned.m16n8k8.row.col.f32.tf32.tf32.f32 "
        "{%0,%1,%2,%3}, {%4,%5,%6,%7}, {%8,%9}, {%0,%1,%2,%3};"
        : "+f"(c[0]), "+f"(c[1]), "+f"(c[2]), "+f"(c[3])
        : "r"(a0), "r"(a1), "r"(a2), "r"(a3), "r"(b0), "r"(b1));
}

// ---------------------------------------------------------------------------
__global__ __launch_bounds__(256) void maskpack(const int* __restrict__ mask) {
    int idx = blockIdx.x * 256 + threadIdx.x;
    int r = idx >> 6, wc = idx & 63;
    const int4* p = (const int4*)(mask + (size_t)r * S_ + wc * 32);
    unsigned bits = 0;
#pragma unroll
    for (int i = 0; i < 8; ++i) {
        int4 m = __ldg(p + i);
        bits |= (unsigned)(m.x != 0) << (4 * i)
              | (unsigned)(m.y != 0) << (4 * i + 1)
              | (unsigned)(m.z != 0) << (4 * i + 2)
              | (unsigned)(m.w != 0) << (4 * i + 3);
    }
    g_Mb[idx] = bits;
}

// Pre-round a float array to tf32 bit patterns (one-time).
__global__ __launch_bounds__(256) void conv_tf(const float* __restrict__ in,
                                               float* __restrict__ outp) {
    int i = (blockIdx.x * 256 + threadIdx.x) * 4;
    float4 v = *(const float4*)(in + i);
    uint4 o;
    o.x = f2tf(v.x); o.y = f2tf(v.y); o.z = f2tf(v.z); o.w = f2tf(v.w);
    *(uint4*)(outp + i) = o;
}

// ---------------------------------------------------------------------------
// Tensor-core GEMM: C[M,N] = A[M,1024] @ W[N,1024]^T + bias
// Block 128x128, BK=32, double-buffered smem, register prefetch, ONE barrier
// per k-iter. Operands pre-rounded to tf32 -> raw STS.128 staging, no cvt.
// 8 warps (2x4), warp tile 64x32. smem stride 36 (conflict-free frags).
// MODE 0: A=g_X, N=3072, scatter tf32-rounded into g_Q/g_K/g_V.
// MODE 1: A=g_C, N=1024, write raw to out.
// ---------------------------------------------------------------------------
template <int MODE>
__global__ __launch_bounds__(256, 2) void gemm_tc(const float* __restrict__ A,
                                                  const float* __restrict__ W,
                                                  const float* __restrict__ bias,
                                                  float* __restrict__ out) {
    extern __shared__ unsigned sh[];
    unsigned* As = sh;                  // [2][128][36]
    unsigned* Bs = sh + 2 * 128 * 36;   // [2][128][36]

    const int m0 = blockIdx.y * 128;
    const int n0 = blockIdx.x * 128;
    const int t = threadIdx.x;
    const int w = t >> 5;
    const int lane = t & 31;
    const int g = lane >> 2;
    const int t4 = lane & 3;
    const int wm = (w >> 2) * 64;
    const int wn = (w & 3) * 32;

    const int lrow = t >> 3;      // 0..31
    const int lseg = t & 7;       // 0..7

    const float* Aptr = (MODE == 1 ? g_C : A);

    uint4 ar[4], br[4];
    // prologue: load k-tile 0
#pragma unroll
    for (int i = 0; i < 4; ++i) {
        int row = lrow + i * 32;
        ar[i] = *(const uint4*)(Aptr + (size_t)(m0 + row) * D_ + lseg * 4);
        br[i] = *(const uint4*)(W + (size_t)(n0 + row) * D_ + lseg * 4);
    }
#pragma unroll
    for (int i = 0; i < 4; ++i) {
        int row = lrow + i * 32;
        *(uint4*)&As[row * 36 + lseg * 4] = ar[i];
        *(uint4*)&Bs[row * 36 + lseg * 4] = br[i];
    }
    __syncthreads();

    float acc[4][4][4];
#pragma unroll
    for (int mt = 0; mt < 4; ++mt)
#pragma unroll
        for (int nt = 0; nt < 4; ++nt)
#pragma unroll
            for (int i = 0; i < 4; ++i) acc[mt][nt][i] = 0.0f;

    for (int k0 = 0; k0 < 32; ++k0) {
        const int kb = (k0 & 1) * 128 * 36;
        if (k0 < 31) {
            int kofs = (k0 + 1) * 32;
#pragma unroll
            for (int i = 0; i < 4; ++i) {
                int row = lrow + i * 32;
                ar[i] = *(const uint4*)(Aptr + (size_t)(m0 + row) * D_ + kofs + lseg * 4);
                br[i] = *(const uint4*)(W + (size_t)(n0 + row) * D_ + kofs + lseg * 4);
            }
        }
#pragma unroll
        for (int ks = 0; ks < 4; ++ks) {
            unsigned a[4][4];
#pragma unroll
            for (int mt = 0; mt < 4; ++mt) {
                const unsigned* q = &As[kb + (wm + mt * 16) * 36 + ks * 8];
                a[mt][0] = q[g * 36 + t4];
                a[mt][1] = q[(g + 8) * 36 + t4];
                a[mt][2] = q[g * 36 + t4 + 4];
                a[mt][3] = q[(g + 8) * 36 + t4 + 4];
            }
#pragma unroll
            for (int nt = 0; nt < 4; ++nt) {
                unsigned b0 = Bs[kb + (wn + nt * 8 + g) * 36 + ks * 8 + t4];
                unsigned b1 = Bs[kb + (wn + nt * 8 + g) * 36 + ks * 8 + t4 + 4];
#pragma unroll
                for (int mt = 0; mt < 4; ++mt)
                    mma_tf32(acc[mt][nt], a[mt][0], a[mt][1], a[mt][2], a[mt][3], b0, b1);
            }
        }
        if (k0 < 31) {
            const int nb = ((k0 + 1) & 1) * 128 * 36;
#pragma unroll
            for (int i = 0; i < 4; ++i) {
                int row = lrow + i * 32;
                *(uint4*)&As[nb + row * 36 + lseg * 4] = ar[i];
                *(uint4*)&Bs[nb + row * 36 + lseg * 4] = br[i];
            }
        }
        __syncthreads();
    }

    // epilogue
#pragma unroll
    for (int mt = 0; mt < 4; ++mt) {
#pragma unroll
        for (int nt = 0; nt < 4; ++nt) {
            int ncol = n0 + wn + nt * 8 + 2 * t4;
            float bx = __ldg(&bias[ncol]);
            float by = __ldg(&bias[ncol + 1]);
#pragma unroll
            for (int rr = 0; rr < 2; ++rr) {
                int m = m0 + wm + mt * 16 + g + rr * 8;
                float vx = acc[mt][nt][rr * 2] + bx;
                float vy = acc[mt][nt][rr * 2 + 1] + by;
                if (MODE == 0) {
                    int bb = m >> 11, ss = m & 2047;
                    int h = ncol / 192;
                    int rem = ncol - h * 192;
                    int part = rem >> 6;
                    int d = rem & 63;
                    size_t dst = (((size_t)(bb * H_ + h)) * S_ + ss) * HD_ + d;
                    float* dstp = (part == 0 ? g_Q : (part == 1 ? g_K : g_V));
                    dstp[dst] = __uint_as_float(f2tf(vx));     // pre-round for attn
                    dstp[dst + 1] = __uint_as_float(f2tf(vy));
                } else {
                    *(float2*)&out[(size_t)m * D_ + ncol] = make_float2(vx, vy);
                }
            }
        }
    }
}

// ---------------------------------------------------------------------------
// Flash attention, tf32 mma. grid=(S/128, B*H), 256 threads.
// Double-buffered K/V smem + register prefetch, ONE barrier per k-tile.
// Q/K/V pre-rounded -> raw STS.128 staging, no cvt. Base-2 softmax (ex2),
// stats in registers. Qs/Ks stride 68, Vs stride 72. Mask from g_Mb bits.
// ---------------------------------------------------------------------------
__global__ __launch_bounds__(256, 2) void attn_tc() {
    extern __shared__ unsigned sh[];
    unsigned* Qs = sh;                        // [128][68]
    unsigned* Ks = sh + 128 * 68;             // [2][64][68]
    unsigned* Vs = Ks + 2 * 64 * 68;          // [2][64][72]

    const int bh = blockIdx.y;
    const int q0 = blockIdx.x * 128;
    const int t = threadIdx.x;
    const int w = t >> 5;
    const int lane = t & 31;
    const int g = lane >> 2;
    const int t4 = lane & 3;

    const size_t base = (size_t)bh * (S_ * HD_);
    const float* Qg = g_Q + base;
    const float* Kg = g_K + base;
    const float* Vg = g_V + base;

    const int lrow = t >> 4;   // 0..15
    const int lseg = t & 15;   // 0..15

    // stage Q tile (raw, pre-rounded)
#pragma unroll
    for (int i = 0; i < 8; ++i) {
        int idx = t + i * 256;
        int row = idx >> 4, seg = idx & 15;
        *(uint4*)&Qs[row * 68 + seg * 4] =
            *(const uint4*)(Qg + (size_t)(q0 + row) * HD_ + seg * 4);
    }

    // stage K/V tile 0 into buffer 0
    uint4 kr[4], vr[4];
#pragma unroll
    for (int i = 0; i < 4; ++i) {
        int row = lrow + i * 16;
        kr[i] = *(const uint4*)(Kg + (size_t)row * HD_ + lseg * 4);
        vr[i] = *(const uint4*)(Vg + (size_t)row * HD_ + lseg * 4);
    }
#pragma unroll
    for (int i = 0; i < 4; ++i) {
        int row = lrow + i * 16;
        *(uint4*)&Ks[row * 68 + lseg * 4] = kr[i];
        *(uint4*)&Vs[row * 72 + lseg * 4] = vr[i];
    }

    const int qrow0 = q0 + w * 16 + g;
    const int qrow1 = qrow0 + 8;
    const unsigned* mbp0 = g_Mb + (size_t)qrow0 * 64;
    const unsigned* mbp1 = g_Mb + (size_t)qrow1 * 64;

    float o[8][4];
#pragma unroll
    for (int nt = 0; nt < 8; ++nt)
#pragma unroll
        for (int i = 0; i < 4; ++i) o[nt][i] = 0.0f;
    float m0s = -INFINITY, m1s = -INFINITY, l0 = 0.0f, l1 = 0.0f;

    __syncthreads();

    for (int j = 0; j < 32; ++j) {
        const int kbK = (j & 1) * 64 * 68;
        const int kbV = (j & 1) * 64 * 72;
        if (j < 31) {
            const float* Kn = Kg + (size_t)(j + 1) * 64 * HD_;
            const float* Vn = Vg + (size_t)(j + 1) * 64 * HD_;
#pragma unroll
            for (int i = 0; i < 4; ++i) {
                int row = lrow + i * 16;
                kr[i] = *(const uint4*)(Kn + (size_t)row * HD_ + lseg * 4);
                vr[i] = *(const uint4*)(Vn + (size_t)row * HD_ + lseg * 4);
            }
        }
        uint2 mb0 = *(const uint2*)(mbp0 + j * 2);
        uint2 mb1 = *(const uint2*)(mbp1 + j * 2);

        // S = Q @ K^T
        float sc[8][4];
#pragma unroll
        for (int nt = 0; nt < 8; ++nt)
#pragma unroll
            for (int i = 0; i < 4; ++i) sc[nt][i] = 0.0f;
#pragma unroll
        for (int ks = 0; ks < 8; ++ks) {
            const unsigned* qb = &Qs[(w * 16) * 68 + ks * 8];
            unsigned a0 = qb[g * 68 + t4];
            unsigned a1 = qb[(g + 8) * 68 + t4];
            unsigned a2 = qb[g * 68 + t4 + 4];
            unsigned a3 = qb[(g + 8) * 68 + t4 + 4];
#pragma unroll
            for (int nt = 0; nt < 8; ++nt) {
                unsigned b0 = Ks[kbK + (nt * 8 + g) * 68 + ks * 8 + t4];
                unsigned b1 = Ks[kbK + (nt * 8 + g) * 68 + ks * 8 + t4 + 4];
                mma_tf32(sc[nt], a0, a1, a2, a3, b0, b1);
            }
        }

        // scale (base-2) + mask from bit matrix
#pragma unroll
        for (int nt = 0; nt < 8; ++nt) {
            unsigned w0 = (nt < 4) ? mb0.x : mb0.y;
            unsigned w1 = (nt < 4) ? mb1.x : mb1.y;
            int shv = (nt & 3) * 8 + 2 * t4;
            unsigned b0 = w0 >> shv;
            unsigned b1 = w1 >> shv;
            sc[nt][0] = (b0 & 1) ? sc[nt][0] * SCALE2 : NEGINF;
            sc[nt][1] = (b0 & 2) ? sc[nt][1] * SCALE2 : NEGINF;
            sc[nt][2] = (b1 & 1) ? sc[nt][2] * SCALE2 : NEGINF;
            sc[nt][3] = (b1 & 2) ? sc[nt][3] * SCALE2 : NEGINF;
        }

        // online softmax (register stats, base-2)
        float mx0 = -INFINITY, mx1 = -INFINITY;
#pragma unroll
        for (int nt = 0; nt < 8; ++nt) {
            mx0 = fmaxf(mx0, fmaxf(sc[nt][0], sc[nt][1]));
            mx1 = fmaxf(mx1, fmaxf(sc[nt][2], sc[nt][3]));
        }
        mx0 = fmaxf(mx0, __shfl_xor_sync(0xffffffffu, mx0, 1));
        mx0 = fmaxf(mx0, __shfl_xor_sync(0xffffffffu, mx0, 2));
        mx1 = fmaxf(mx1, __shfl_xor_sync(0xffffffffu, mx1, 1));
        mx1 = fmaxf(mx1, __shfl_xor_sync(0xffffffffu, mx1, 2));
        float mn0 = fmaxf(m0s, mx0), mn1 = fmaxf(m1s, mx1);
        float al0 = ex2(m0s - mn0), al1 = ex2(m1s - mn1);
        m0s = mn0; m1s = mn1;
        float rs0 = 0.0f, rs1 = 0.0f;
#pragma unroll
        for (int nt = 0; nt < 8; ++nt) {
            sc[nt][0] = ex2(sc[nt][0] - mn0);
            sc[nt][1] = ex2(sc[nt][1] - mn0);
            sc[nt][2] = ex2(sc[nt][2] - mn1);
            sc[nt][3] = ex2(sc[nt][3] - mn1);
            rs0 += sc[nt][0] + sc[nt][1];
            rs1 += sc[nt][2] + sc[nt][3];
        }
        rs0 += __shfl_xor_sync(0xffffffffu, rs0, 1);
        rs0 += __shfl_xor_sync(0xffffffffu, rs0, 2);
        rs1 += __shfl_xor_sync(0xffffffffu, rs1, 1);
        rs1 += __shfl_xor_sync(0xffffffffu, rs1, 2);
        l0 = al0 * l0 + rs0;
        l1 = al1 * l1 + rs1;
#pragma unroll
        for (int nt = 0; nt < 8; ++nt) {
            o[nt][0] *= al0; o[nt][1] *= al0;
            o[nt][2] *= al1; o[nt][3] *= al1;
        }

        // O += P @ V : relayout P C-frag -> A-frag via shfl
        const int s0l = (lane & ~3) | (t4 >> 1);
        const int s1l = s0l + 2;
        const bool odd = (t4 & 1);
#pragma unroll
        for (int kt = 0; kt < 8; ++kt) {
            float e00 = __shfl_sync(0xffffffffu, sc[kt][0], s0l);
            float e01 = __shfl_sync(0xffffffffu, sc[kt][1], s0l);
            float e10 = __shfl_sync(0xffffffffu, sc[kt][2], s0l);
            float e11 = __shfl_sync(0xffffffffu, sc[kt][3], s0l);
            float f00 = __shfl_sync(0xffffffffu, sc[kt][0], s1l);
            float f01 = __shfl_sync(0xffffffffu, sc[kt][1], s1l);
            float f10 = __shfl_sync(0xffffffffu, sc[kt][2], s1l);
            float f11 = __shfl_sync(0xffffffffu, sc[kt][3], s1l);
            unsigned a0 = f2tf(odd ? e01 : e00);
            unsigned a1 = f2tf(odd ? e11 : e10);
            unsigned a2 = f2tf(odd ? f01 : f00);
            unsigned a3 = f2tf(odd ? f11 : f10);
#pragma unroll
            for (int nt = 0; nt < 8; ++nt) {
                unsigned b0 = Vs[kbV + (kt * 8 + t4) * 72 + nt * 8 + g];
                unsigned b1 = Vs[kbV + (kt * 8 + t4 + 4) * 72 + nt * 8 + g];
                mma_tf32(o[nt], a0, a1, a2, a3, b0, b1);
            }
        }

        if (j < 31) {
            const int nbK = ((j + 1) & 1) * 64 * 68;
            const int nbV = ((j + 1) & 1) * 64 * 72;
#pragma unroll
            for (int i = 0; i < 4; ++i) {
                int row = lrow + i * 16;
                *(uint4*)&Ks[nbK + row * 68 + lseg * 4] = kr[i];
                *(uint4*)&Vs[nbV + row * 72 + lseg * 4] = vr[i];
            }
        }
        __syncthreads();
    }

    // epilogue: normalize, tf32-round, write ctx [B,S,D]
    const int bb = bh >> 4;
    const int h = bh & 15;
    float inv0 = 1.0f / l0, inv1 = 1.0f / l1;
#pragma unroll
    for (int nt = 0; nt < 8; ++nt) {
        int dcol = h * 64 + nt * 8 + 2 * t4;
        size_t r0 = ((size_t)bb * S_ + qrow0) * D_ + dcol;
        size_t r1 = ((size_t)bb * S_ + qrow1) * D_ + dcol;
        float2 v0 = make_float2(__uint_as_float(f2tf(o[nt][0] * inv0)),
                                __uint_as_float(f2tf(o[nt][1] * inv0)));
        float2 v1 = make_float2(__uint_as_float(f2tf(o[nt][2] * inv1)),
                                __uint_as_float(f2tf(o[nt][3] * inv1)));
        *(float2*)&g_C[r0] = v0;
        *(float2*)&g_C[r1] = v1;
    }
}

// ---------------------------------------------------------------------------
extern "C" void kernel_launch(void* const* d_in, const int* in_sizes, int n_in,
                              void* d_out, int out_size) {
    const float* x     = (const float*)d_in[0];
    const int*   mask  = (const int*)d_in[1];
    const float* w_qkv = (const float*)d_in[2];
    const float* b_qkv = (const float*)d_in[3];
    const float* w_o   = (const float*)d_in[4];
    const float* b_o   = (const float*)d_in[5];
    float* out = (float*)d_out;

    const int gemm_smem = 4 * 128 * 36 * (int)sizeof(unsigned);  // 73728
    const int attn_smem = (128 * 68 + 2 * 64 * 68 + 2 * 64 * 72) * (int)sizeof(unsigned);

    cudaFuncSetAttribute(gemm_tc<0>, cudaFuncAttributeMaxDynamicSharedMemorySize, gemm_smem);
    cudaFuncSetAttribute(gemm_tc<1>, cudaFuncAttributeMaxDynamicSharedMemorySize, gemm_smem);
    cudaFuncSetAttribute(attn_tc, cudaFuncAttributeMaxDynamicSharedMemorySize, attn_smem);

    // 0) one-time prep: pack mask bits; pre-round inputs/weights to tf32
    maskpack<<<S_ * (S_ / 32) / 256, 256>>>(mask);
    conv_tf<<<B_ * S_ * D_ / 1024, 256>>>(x, g_X);
    conv_tf<<<3 * D_ * D_ / 1024, 256>>>(w_qkv, g_W1);
    conv_tf<<<D_ * D_ / 1024, 256>>>(w_o, g_W2);

    // 1) QKV projection
    gemm_tc<0><<<dim3(3072 / 128, 4096 / 128), 256, gemm_smem>>>(g_X, g_W1, b_qkv, nullptr);

    // 2) flash attention
    attn_tc<<<dim3(S_ / 128, B_ * H_), 256, attn_smem>>>();

    // 3) output projection
    gemm_tc<1><<<dim3(1024 / 128, 4096 / 128), 256, gemm_smem>>>(nullptr, g_W2, b_o, out);
}

// round 6
// speedup vs baseline: 16.2977x; 9.7242x over previous
#include <cuda_runtime.h>
#include <math.h>

#define B_ 2
#define S_ 2048
#define D_ 1024
#define H_ 16
#define HD_ 64
#define NEGINF (-9000000000000000.0f)
// logits scale folded with log2(e): softmax computed in base-2 domain
#define SCALE2 0.1803368801111204f

// Scratch (device globals: allocation-free rule)
__device__ float g_Q[B_ * H_ * S_ * HD_];
__device__ float g_K[B_ * H_ * S_ * HD_];
__device__ float g_V[B_ * H_ * S_ * HD_];
__device__ float g_C[B_ * S_ * D_];
__device__ unsigned g_Mb[S_ * (S_ / 32)];   // bit-packed mask, 512 KB

__device__ __forceinline__ unsigned f2tf(float x) {
    unsigned r;
    asm("cvt.rna.tf32.f32 %0, %1;" : "=r"(r) : "f"(x));
    return r;
}
__device__ __forceinline__ float ex2(float x) {
    float y;
    asm("ex2.approx.f32 %0, %1;" : "=f"(y) : "f"(x));
    return y;
}
__device__ __forceinline__ void mma_tf32(float c[4], unsigned a0, unsigned a1,
                                         unsigned a2, unsigned a3,
                                         unsigned b0, unsigned b1) {
    asm volatile(
        "mma.sync.aligned.m16n8k8.row.col.f32.tf32.tf32.f32 "
        "{%0,%1,%2,%3}, {%4,%5,%6,%7}, {%8,%9}, {%0,%1,%2,%3};"
        : "+f"(c[0]), "+f"(c[1]), "+f"(c[2]), "+f"(c[3])
        : "r"(a0), "r"(a1), "r"(a2), "r"(a3), "r"(b0), "r"(b1));
}

// ---------------------------------------------------------------------------
// Pack mask[1,1,S,S] (int32) into bit matrix g_Mb[S][S/32].
// ---------------------------------------------------------------------------
__global__ __launch_bounds__(256) void maskpack(const int* __restrict__ mask) {
    int idx = blockIdx.x * 256 + threadIdx.x;   // word index, 131072 total
    int r = idx >> 6, wc = idx & 63;
    const int4* p = (const int4*)(mask + (size_t)r * S_ + wc * 32);
    unsigned bits = 0;
#pragma unroll
    for (int i = 0; i < 8; ++i) {
        int4 m = __ldg(p + i);
        bits |= (unsigned)(m.x != 0) << (4 * i)
              | (unsigned)(m.y != 0) << (4 * i + 1)
              | (unsigned)(m.z != 0) << (4 * i + 2)
              | (unsigned)(m.w != 0) << (4 * i + 3);
    }
    g_Mb[idx] = bits;
}

// ---------------------------------------------------------------------------
// Tensor-core GEMM: C[M,N] = A[M,1024] @ W[N,1024]^T + bias
// Block 128x128, BK=32, double-buffered smem, register prefetch, ONE barrier
// per k-iter. 8 warps (2x4), warp tile 64x32 (4 m16 x 4 n8).
// smem stride 36 -> conflict-free frag loads (bank = 4g+t4) and STS.
// MODE 0: A=x, N=3072, scatter into g_Q/g_K/g_V. MODE 1: A=g_C, N=1024.
// ---------------------------------------------------------------------------
template <int MODE>
__global__ __launch_bounds__(256, 2) void gemm_tc(const float* __restrict__ A,
                                                  const float* __restrict__ W,
                                                  const float* __restrict__ bias,
                                                  float* __restrict__ out) {
    extern __shared__ unsigned sh[];
    unsigned* As = sh;                  // [2][128][36]
    unsigned* Bs = sh + 2 * 128 * 36;   // [2][128][36]

    const int m0 = blockIdx.y * 128;
    const int n0 = blockIdx.x * 128;
    const int t = threadIdx.x;
    const int w = t >> 5;
    const int lane = t & 31;
    const int g = lane >> 2;
    const int t4 = lane & 3;
    const int wm = (w >> 2) * 64;
    const int wn = (w & 3) * 32;

    const int lrow = t >> 3;      // 0..31 base row step (idx>>3)
    const int lseg = t & 7;       // 0..7

    const float* Aptr = (MODE == 1 ? g_C : A);

    float4 ar[4], br[4];
    // prologue: load k-tile 0
#pragma unroll
    for (int i = 0; i < 4; ++i) {
        int row = lrow + i * 32;
        ar[i] = *(const float4*)(Aptr + (size_t)(m0 + row) * D_ + lseg * 4);
        br[i] = *(const float4*)(W + (size_t)(n0 + row) * D_ + lseg * 4);
    }
#pragma unroll
    for (int i = 0; i < 4; ++i) {
        int row = lrow + i * 32;
        unsigned* pa = &As[row * 36 + lseg * 4];
        pa[0] = f2tf(ar[i].x); pa[1] = f2tf(ar[i].y);
        pa[2] = f2tf(ar[i].z); pa[3] = f2tf(ar[i].w);
        unsigned* pb = &Bs[row * 36 + lseg * 4];
        pb[0] = f2tf(br[i].x); pb[1] = f2tf(br[i].y);
        pb[2] = f2tf(br[i].z); pb[3] = f2tf(br[i].w);
    }
    __syncthreads();

    float acc[4][4][4];
#pragma unroll
    for (int mt = 0; mt < 4; ++mt)
#pragma unroll
        for (int nt = 0; nt < 4; ++nt)
#pragma unroll
            for (int i = 0; i < 4; ++i) acc[mt][nt][i] = 0.0f;

    for (int k0 = 0; k0 < 32; ++k0) {
        const int kb = (k0 & 1) * 128 * 36;
        if (k0 < 31) {
            int kofs = (k0 + 1) * 32;
#pragma unroll
            for (int i = 0; i < 4; ++i) {
                int row = lrow + i * 32;
                ar[i] = *(const float4*)(Aptr + (size_t)(m0 + row) * D_ + kofs + lseg * 4);
                br[i] = *(const float4*)(W + (size_t)(n0 + row) * D_ + kofs + lseg * 4);
            }
        }
#pragma unroll
        for (int ks = 0; ks < 4; ++ks) {
            unsigned a[4][4];
#pragma unroll
            for (int mt = 0; mt < 4; ++mt) {
                const unsigned* q = &As[kb + (wm + mt * 16) * 36 + ks * 8];
                a[mt][0] = q[g * 36 + t4];
                a[mt][1] = q[(g + 8) * 36 + t4];
                a[mt][2] = q[g * 36 + t4 + 4];
                a[mt][3] = q[(g + 8) * 36 + t4 + 4];
            }
#pragma unroll
            for (int nt = 0; nt < 4; ++nt) {
                unsigned b0 = Bs[kb + (wn + nt * 8 + g) * 36 + ks * 8 + t4];
                unsigned b1 = Bs[kb + (wn + nt * 8 + g) * 36 + ks * 8 + t4 + 4];
#pragma unroll
                for (int mt = 0; mt < 4; ++mt)
                    mma_tf32(acc[mt][nt], a[mt][0], a[mt][1], a[mt][2], a[mt][3], b0, b1);
            }
        }
        if (k0 < 31) {
            const int nb = ((k0 + 1) & 1) * 128 * 36;
#pragma unroll
            for (int i = 0; i < 4; ++i) {
                int row = lrow + i * 32;
                unsigned* pa = &As[nb + row * 36 + lseg * 4];
                pa[0] = f2tf(ar[i].x); pa[1] = f2tf(ar[i].y);
                pa[2] = f2tf(ar[i].z); pa[3] = f2tf(ar[i].w);
                unsigned* pb = &Bs[nb + row * 36 + lseg * 4];
                pb[0] = f2tf(br[i].x); pb[1] = f2tf(br[i].y);
                pb[2] = f2tf(br[i].z); pb[3] = f2tf(br[i].w);
            }
        }
        __syncthreads();
    }

    // epilogue
#pragma unroll
    for (int mt = 0; mt < 4; ++mt) {
#pragma unroll
        for (int nt = 0; nt < 4; ++nt) {
            int ncol = n0 + wn + nt * 8 + 2 * t4;
            float bx = __ldg(&bias[ncol]);
            float by = __ldg(&bias[ncol + 1]);
#pragma unroll
            for (int rr = 0; rr < 2; ++rr) {
                int m = m0 + wm + mt * 16 + g + rr * 8;
                float vx = acc[mt][nt][rr * 2] + bx;
                float vy = acc[mt][nt][rr * 2 + 1] + by;
                if (MODE == 0) {
                    int bb = m >> 11, ss = m & 2047;
                    int h = ncol / 192;
                    int rem = ncol - h * 192;
                    int part = rem >> 6;
                    int d = rem & 63;
                    size_t dst = (((size_t)(bb * H_ + h)) * S_ + ss) * HD_ + d;
                    float* dstp = (part == 0 ? g_Q : (part == 1 ? g_K : g_V));
                    dstp[dst] = vx;
                    dstp[dst + 1] = vy;
                } else {
                    *(float2*)&out[(size_t)m * D_ + ncol] = make_float2(vx, vy);
                }
            }
        }
    }
}

// ---------------------------------------------------------------------------
// Flash attention, tf32 mma. grid=(S/128, B*H), 256 threads.
// Double-buffered K/V smem + register prefetch, ONE barrier per k-tile.
// Mask read from bit-packed g_Mb. Warp owns 16 full q-rows -> softmax stats
// in registers, computed in base-2 domain (scale folded with log2 e, ex2).
// Qs/Ks stride 68, Vs stride 72 (conflict-free).
// ---------------------------------------------------------------------------
__global__ __launch_bounds__(256, 2) void attn_tc() {
    extern __shared__ unsigned sh[];
    unsigned* Qs = sh;                        // [128][68]
    unsigned* Ks = sh + 128 * 68;             // [2][64][68]
    unsigned* Vs = Ks + 2 * 64 * 68;          // [2][64][72]

    const int bh = blockIdx.y;
    const int q0 = blockIdx.x * 128;
    const int t = threadIdx.x;
    const int w = t >> 5;
    const int lane = t & 31;
    const int g = lane >> 2;
    const int t4 = lane & 3;

    const size_t base = (size_t)bh * (S_ * HD_);
    const float* Qg = g_Q + base;
    const float* Kg = g_K + base;
    const float* Vg = g_V + base;

    const int lrow = t >> 4;   // 0..15
    const int lseg = t & 15;   // 0..15

    // stage Q tile
#pragma unroll
    for (int i = 0; i < 8; ++i) {
        int idx = t + i * 256;
        int row = idx >> 4, seg = idx & 15;
        float4 v = *(const float4*)(Qg + (size_t)(q0 + row) * HD_ + seg * 4);
        unsigned* p = &Qs[row * 68 + seg * 4];
        p[0] = f2tf(v.x); p[1] = f2tf(v.y); p[2] = f2tf(v.z); p[3] = f2tf(v.w);
    }

    // stage K/V tile 0 into buffer 0
    float4 kr[4], vr[4];
#pragma unroll
    for (int i = 0; i < 4; ++i) {
        int row = lrow + i * 16;
        kr[i] = *(const float4*)(Kg + (size_t)row * HD_ + lseg * 4);
        vr[i] = *(const float4*)(Vg + (size_t)row * HD_ + lseg * 4);
    }
#pragma unroll
    for (int i = 0; i < 4; ++i) {
        int row = lrow + i * 16;
        unsigned* p = &Ks[row * 68 + lseg * 4];
        p[0] = f2tf(kr[i].x); p[1] = f2tf(kr[i].y); p[2] = f2tf(kr[i].z); p[3] = f2tf(kr[i].w);
        unsigned* q = &Vs[row * 72 + lseg * 4];
        q[0] = f2tf(vr[i].x); q[1] = f2tf(vr[i].y); q[2] = f2tf(vr[i].z); q[3] = f2tf(vr[i].w);
    }

    const int qrow0 = q0 + w * 16 + g;
    const int qrow1 = qrow0 + 8;
    const unsigned* mbp0 = g_Mb + (size_t)qrow0 * 64;
    const unsigned* mbp1 = g_Mb + (size_t)qrow1 * 64;

    float o[8][4];
#pragma unroll
    for (int nt = 0; nt < 8; ++nt)
#pragma unroll
        for (int i = 0; i < 4; ++i) o[nt][i] = 0.0f;
    float m0s = -INFINITY, m1s = -INFINITY, l0 = 0.0f, l1 = 0.0f;

    __syncthreads();

    for (int j = 0; j < 32; ++j) {
        const int kbK = (j & 1) * 64 * 68;
        const int kbV = (j & 1) * 64 * 72;
        if (j < 31) {
            const float* Kn = Kg + (size_t)(j + 1) * 64 * HD_;
            const float* Vn = Vg + (size_t)(j + 1) * 64 * HD_;
#pragma unroll
            for (int i = 0; i < 4; ++i) {
                int row = lrow + i * 16;
                kr[i] = *(const float4*)(Kn + (size_t)row * HD_ + lseg * 4);
                vr[i] = *(const float4*)(Vn + (size_t)row * HD_ + lseg * 4);
            }
        }
        uint2 mb0 = *(const uint2*)(mbp0 + j * 2);
        uint2 mb1 = *(const uint2*)(mbp1 + j * 2);

        // S = Q @ K^T
        float sc[8][4];
#pragma unroll
        for (int nt = 0; nt < 8; ++nt)
#pragma unroll
            for (int i = 0; i < 4; ++i) sc[nt][i] = 0.0f;
#pragma unroll
        for (int ks = 0; ks < 8; ++ks) {
            const unsigned* qb = &Qs[(w * 16) * 68 + ks * 8];
            unsigned a0 = qb[g * 68 + t4];
            unsigned a1 = qb[(g + 8) * 68 + t4];
            unsigned a2 = qb[g * 68 + t4 + 4];
            unsigned a3 = qb[(g + 8) * 68 + t4 + 4];
#pragma unroll
            for (int nt = 0; nt < 8; ++nt) {
                unsigned b0 = Ks[kbK + (nt * 8 + g) * 68 + ks * 8 + t4];
                unsigned b1 = Ks[kbK + (nt * 8 + g) * 68 + ks * 8 + t4 + 4];
                mma_tf32(sc[nt], a0, a1, a2, a3, b0, b1);
            }
        }

        // scale (base-2 domain) + mask from bit matrix
#pragma unroll
        for (int nt = 0; nt < 8; ++nt) {
            unsigned w0 = (nt < 4) ? mb0.x : mb0.y;
            unsigned w1 = (nt < 4) ? mb1.x : mb1.y;
            int shv = (nt & 3) * 8 + 2 * t4;
            unsigned b0 = w0 >> shv;
            unsigned b1 = w1 >> shv;
            sc[nt][0] = (b0 & 1) ? sc[nt][0] * SCALE2 : NEGINF;
            sc[nt][1] = (b0 & 2) ? sc[nt][1] * SCALE2 : NEGINF;
            sc[nt][2] = (b1 & 1) ? sc[nt][2] * SCALE2 : NEGINF;
            sc[nt][3] = (b1 & 2) ? sc[nt][3] * SCALE2 : NEGINF;
        }

        // online softmax (register stats, base-2)
        float mx0 = -INFINITY, mx1 = -INFINITY;
#pragma unroll
        for (int nt = 0; nt < 8; ++nt) {
            mx0 = fmaxf(mx0, fmaxf(sc[nt][0], sc[nt][1]));
            mx1 = fmaxf(mx1, fmaxf(sc[nt][2], sc[nt][3]));
        }
        mx0 = fmaxf(mx0, __shfl_xor_sync(0xffffffffu, mx0, 1));
        mx0 = fmaxf(mx0, __shfl_xor_sync(0xffffffffu, mx0, 2));
        mx1 = fmaxf(mx1, __shfl_xor_sync(0xffffffffu, mx1, 1));
        mx1 = fmaxf(mx1, __shfl_xor_sync(0xffffffffu, mx1, 2));
        float mn0 = fmaxf(m0s, mx0), mn1 = fmaxf(m1s, mx1);
        float al0 = ex2(m0s - mn0), al1 = ex2(m1s - mn1);
        m0s = mn0; m1s = mn1;
        float rs0 = 0.0f, rs1 = 0.0f;
#pragma unroll
        for (int nt = 0; nt < 8; ++nt) {
            sc[nt][0] = ex2(sc[nt][0] - mn0);
            sc[nt][1] = ex2(sc[nt][1] - mn0);
            sc[nt][2] = ex2(sc[nt][2] - mn1);
            sc[nt][3] = ex2(sc[nt][3] - mn1);
            rs0 += sc[nt][0] + sc[nt][1];
            rs1 += sc[nt][2] + sc[nt][3];
        }
        rs0 += __shfl_xor_sync(0xffffffffu, rs0, 1);
        rs0 += __shfl_xor_sync(0xffffffffu, rs0, 2);
        rs1 += __shfl_xor_sync(0xffffffffu, rs1, 1);
        rs1 += __shfl_xor_sync(0xffffffffu, rs1, 2);
        l0 = al0 * l0 + rs0;
        l1 = al1 * l1 + rs1;
#pragma unroll
        for (int nt = 0; nt < 8; ++nt) {
            o[nt][0] *= al0; o[nt][1] *= al0;
            o[nt][2] *= al1; o[nt][3] *= al1;
        }

        // O += P @ V : relayout P C-frag -> A-frag via shfl
        const int s0l = (lane & ~3) | (t4 >> 1);
        const int s1l = s0l + 2;
        const bool odd = (t4 & 1);
#pragma unroll
        for (int kt = 0; kt < 8; ++kt) {
            float e00 = __shfl_sync(0xffffffffu, sc[kt][0], s0l);
            float e01 = __shfl_sync(0xffffffffu, sc[kt][1], s0l);
            float e10 = __shfl_sync(0xffffffffu, sc[kt][2], s0l);
            float e11 = __shfl_sync(0xffffffffu, sc[kt][3], s0l);
            float f00 = __shfl_sync(0xffffffffu, sc[kt][0], s1l);
            float f01 = __shfl_sync(0xffffffffu, sc[kt][1], s1l);
            float f10 = __shfl_sync(0xffffffffu, sc[kt][2], s1l);
            float f11 = __shfl_sync(0xffffffffu, sc[kt][3], s1l);
            unsigned a0 = f2tf(odd ? e01 : e00);
            unsigned a1 = f2tf(odd ? e11 : e10);
            unsigned a2 = f2tf(odd ? f01 : f00);
            unsigned a3 = f2tf(odd ? f11 : f10);
#pragma unroll
            for (int nt = 0; nt < 8; ++nt) {
                unsigned b0 = Vs[kbV + (kt * 8 + t4) * 72 + nt * 8 + g];
                unsigned b1 = Vs[kbV + (kt * 8 + t4 + 4) * 72 + nt * 8 + g];
                mma_tf32(o[nt], a0, a1, a2, a3, b0, b1);
            }
        }

        if (j < 31) {
            const int nbK = ((j + 1) & 1) * 64 * 68;
            const int nbV = ((j + 1) & 1) * 64 * 72;
#pragma unroll
            for (int i = 0; i < 4; ++i) {
                int row = lrow + i * 16;
                unsigned* p = &Ks[nbK + row * 68 + lseg * 4];
                p[0] = f2tf(kr[i].x); p[1] = f2tf(kr[i].y);
                p[2] = f2tf(kr[i].z); p[3] = f2tf(kr[i].w);
                unsigned* q = &Vs[nbV + row * 72 + lseg * 4];
                q[0] = f2tf(vr[i].x); q[1] = f2tf(vr[i].y);
                q[2] = f2tf(vr[i].z); q[3] = f2tf(vr[i].w);
            }
        }
        __syncthreads();
    }

    // epilogue: normalize, write ctx [B,S,D]
    const int bb = bh >> 4;
    const int h = bh & 15;
    float inv0 = 1.0f / l0, inv1 = 1.0f / l1;
#pragma unroll
    for (int nt = 0; nt < 8; ++nt) {
        int dcol = h * 64 + nt * 8 + 2 * t4;
        size_t r0 = ((size_t)bb * S_ + qrow0) * D_ + dcol;
        size_t r1 = ((size_t)bb * S_ + qrow1) * D_ + dcol;
        *(float2*)&g_C[r0] = make_float2(o[nt][0] * inv0, o[nt][1] * inv0);
        *(float2*)&g_C[r1] = make_float2(o[nt][2] * inv1, o[nt][3] * inv1);
    }
}

// ---------------------------------------------------------------------------
extern "C" void kernel_launch(void* const* d_in, const int* in_sizes, int n_in,
                              void* d_out, int out_size) {
    const float* x     = (const float*)d_in[0];
    const int*   mask  = (const int*)d_in[1];
    const float* w_qkv = (const float*)d_in[2];
    const float* b_qkv = (const float*)d_in[3];
    const float* w_o   = (const float*)d_in[4];
    const float* b_o   = (const float*)d_in[5];
    float* out = (float*)d_out;

    const int gemm_smem = 4 * 128 * 36 * (int)sizeof(unsigned);               // 73728
    const int attn_smem = (128 * 68 + 2 * 64 * 68 + 2 * 64 * 72) * (int)sizeof(unsigned); // 106496

    cudaFuncSetAttribute(gemm_tc<0>, cudaFuncAttributeMaxDynamicSharedMemorySize, gemm_smem);
    cudaFuncSetAttribute(gemm_tc<1>, cudaFuncAttributeMaxDynamicSharedMemorySize, gemm_smem);
    cudaFuncSetAttribute(attn_tc, cudaFuncAttributeMaxDynamicSharedMemorySize, attn_smem);

    // 0) pack mask bits
    maskpack<<<S_ * (S_ / 32) / 256, 256>>>(mask);

    // 1) QKV projection
    gemm_tc<0><<<dim3(3072 / 128, 4096 / 128), 256, gemm_smem>>>(x, w_qkv, b_qkv, nullptr);

    // 2) flash attention
    attn_tc<<<dim3(S_ / 128, B_ * H_), 256, attn_smem>>>();

    // 3) output projection
    gemm_tc<1><<<dim3(1024 / 128, 4096 / 128), 256, gemm_smem>>>(nullptr, w_o, b_o, out);
}

// round 8
// speedup vs baseline: 17.2618x; 1.0592x over previous
#include <cuda_runtime.h>
#include <math.h>
#include <cstdint>

#define B_ 2
#define S_ 2048
#define D_ 1024
#define H_ 16
#define HD_ 64
#define NEGINF (-9000000000000000.0f)
#define SCALE2 0.1803368801111204f

// Scratch (device globals: allocation-free rule)
__device__ float g_Q[B_ * H_ * S_ * HD_];
__device__ float g_K[B_ * H_ * S_ * HD_];
__device__ float g_V[B_ * H_ * S_ * HD_];
__device__ float g_C[B_ * S_ * D_];
__device__ unsigned g_Mb[S_ * (S_ / 32)];

__device__ __forceinline__ unsigned f2tf(float x) {
    unsigned r;
    asm("cvt.rna.tf32.f32 %0, %1;" : "=r"(r) : "f"(x));
    return r;
}
__device__ __forceinline__ float ex2(float x) {
    float y;
    asm("ex2.approx.f32 %0, %1;" : "=f"(y) : "f"(x));
    return y;
}
__device__ __forceinline__ void mma_tf32(float c[4], unsigned a0, unsigned a1,
                                         unsigned a2, unsigned a3,
                                         unsigned b0, unsigned b1) {
    asm volatile(
        "mma.sync.aligned.m16n8k8.row.col.f32.tf32.tf32.f32 "
        "{%0,%1,%2,%3}, {%4,%5,%6,%7}, {%8,%9}, {%0,%1,%2,%3};"
        : "+f"(c[0]), "+f"(c[1]), "+f"(c[2]), "+f"(c[3])
        : "r"(a0), "r"(a1), "r"(a2), "r"(a3), "r"(b0), "r"(b1));
}
__device__ __forceinline__ unsigned smem_u32(const void* p) {
    return (unsigned)__cvta_generic_to_shared(p);
}
// ldmatrix x4: four 8x8 b16 tiles == four 8x4 tf32 fragment tiles.
// lane l of tile i receives 32-bit element (row l/4, col l%4).
__device__ __forceinline__ void ldsm4(unsigned r[4], unsigned addr) {
    asm volatile(
        "ldmatrix.sync.aligned.m8n8.x4.shared.b16 {%0,%1,%2,%3}, [%4];"
        : "=r"(r[0]), "=r"(r[1]), "=r"(r[2]), "=r"(r[3]) : "r"(addr));
}

// ---------------------------------------------------------------------------
__global__ __launch_bounds__(256) void maskpack(const int* __restrict__ mask) {
    int idx = blockIdx.x * 256 + threadIdx.x;
    int r = idx >> 6, wc = idx & 63;
    const int4* p = (const int4*)(mask + (size_t)r * S_ + wc * 32);
    unsigned bits = 0;
#pragma unroll
    for (int i = 0; i < 8; ++i) {
        int4 m = __ldg(p + i);
        bits |= (unsigned)(m.x != 0) << (4 * i)
              | (unsigned)(m.y != 0) << (4 * i + 1)
              | (unsigned)(m.z != 0) << (4 * i + 2)
              | (unsigned)(m.w != 0) << (4 * i + 3);
    }
    g_Mb[idx] = bits;
}

// ---------------------------------------------------------------------------
// Tensor-core GEMM: C[M,N] = A[M,1024] @ W[N,1024]^T + bias
// Block 128x128, BK=32, double-buffered smem, register prefetch, ONE barrier
// per k-iter. Fragments loaded via ldmatrix.x4 (A: 1 LDSM per mt/ks,
// B: 2 nt per LDSM). smem stride 36 keeps LDSM conflict-free.
// MODE 0: A=x, N=3072, scatter into g_Q/g_K/g_V. MODE 1: A=g_C, N=1024.
// ---------------------------------------------------------------------------
template <int MODE>
__global__ __launch_bounds__(256, 2) void gemm_tc(const float* __restrict__ A,
                                                  const float* __restrict__ W,
                                                  const float* __restrict__ bias,
                                                  float* __restrict__ out) {
    extern __shared__ unsigned sh[];
    unsigned* As = sh;                  // [2][128][36]
    unsigned* Bs = sh + 2 * 128 * 36;   // [2][128][36]

    const int m0 = blockIdx.y * 128;
    const int n0 = blockIdx.x * 128;
    const int t = threadIdx.x;
    const int w = t >> 5;
    const int lane = t & 31;
    const int g = lane >> 2;
    const int t4 = lane & 3;
    const int wm = (w >> 2) * 64;
    const int wn = (w & 3) * 32;

    const int lrow = t >> 3;      // 0..31
    const int lseg = t & 7;       // 0..7

    // ldmatrix per-lane base offsets (words)
    const int lrow8 = lane & 7;
    const int msel = lane >> 3;
    const unsigned a_base = (wm + ((msel & 1) << 3) + lrow8) * 36 + ((msel >> 1) << 2);
    const unsigned b_base = (wn + ((msel >> 1) << 3) + lrow8) * 36 + ((msel & 1) << 2);
    const unsigned sA = smem_u32(As);
    const unsigned sB = smem_u32(Bs);

    const float* Aptr = (MODE == 1 ? g_C : A);

    float4 ar[4], br[4];
#pragma unroll
    for (int i = 0; i < 4; ++i) {
        int row = lrow + i * 32;
        ar[i] = *(const float4*)(Aptr + (size_t)(m0 + row) * D_ + lseg * 4);
        br[i] = *(const float4*)(W + (size_t)(n0 + row) * D_ + lseg * 4);
    }
#pragma unroll
    for (int i = 0; i < 4; ++i) {
        int row = lrow + i * 32;
        unsigned* pa = &As[row * 36 + lseg * 4];
        pa[0] = f2tf(ar[i].x); pa[1] = f2tf(ar[i].y);
        pa[2] = f2tf(ar[i].z); pa[3] = f2tf(ar[i].w);
        unsigned* pb = &Bs[row * 36 + lseg * 4];
        pb[0] = f2tf(br[i].x); pb[1] = f2tf(br[i].y);
        pb[2] = f2tf(br[i].z); pb[3] = f2tf(br[i].w);
    }
    __syncthreads();

    float acc[4][4][4];
#pragma unroll
    for (int mt = 0; mt < 4; ++mt)
#pragma unroll
        for (int nt = 0; nt < 4; ++nt)
#pragma unroll
            for (int i = 0; i < 4; ++i) acc[mt][nt][i] = 0.0f;

    for (int k0 = 0; k0 < 32; ++k0) {
        const unsigned kbA = sA + (k0 & 1) * (128 * 36 * 4);
        const unsigned kbB = sB + (k0 & 1) * (128 * 36 * 4);
        if (k0 < 31) {
            int kofs = (k0 + 1) * 32;
#pragma unroll
            for (int i = 0; i < 4; ++i) {
                int row = lrow + i * 32;
                ar[i] = *(const float4*)(Aptr + (size_t)(m0 + row) * D_ + kofs + lseg * 4);
                br[i] = *(const float4*)(W + (size_t)(n0 + row) * D_ + kofs + lseg * 4);
            }
        }
#pragma unroll
        for (int ks = 0; ks < 4; ++ks) {
            unsigned a[4][4];
#pragma unroll
            for (int mt = 0; mt < 4; ++mt)
                ldsm4(a[mt], kbA + (a_base + mt * 16 * 36 + ks * 8) * 4);
#pragma unroll
            for (int p = 0; p < 2; ++p) {
                unsigned bb[4];
                ldsm4(bb, kbB + (b_base + p * 16 * 36 + ks * 8) * 4);
#pragma unroll
                for (int mt = 0; mt < 4; ++mt) {
                    mma_tf32(acc[mt][2 * p], a[mt][0], a[mt][1], a[mt][2], a[mt][3],
                             bb[0], bb[1]);
                    mma_tf32(acc[mt][2 * p + 1], a[mt][0], a[mt][1], a[mt][2], a[mt][3],
                             bb[2], bb[3]);
                }
            }
        }
        if (k0 < 31) {
            const int nb = ((k0 + 1) & 1) * 128 * 36;
#pragma unroll
            for (int i = 0; i < 4; ++i) {
                int row = lrow + i * 32;
                unsigned* pa = &As[nb + row * 36 + lseg * 4];
                pa[0] = f2tf(ar[i].x); pa[1] = f2tf(ar[i].y);
                pa[2] = f2tf(ar[i].z); pa[3] = f2tf(ar[i].w);
                unsigned* pb = &Bs[nb + row * 36 + lseg * 4];
                pb[0] = f2tf(br[i].x); pb[1] = f2tf(br[i].y);
                pb[2] = f2tf(br[i].z); pb[3] = f2tf(br[i].w);
            }
        }
        __syncthreads();
    }

    // epilogue
#pragma unroll
    for (int mt = 0; mt < 4; ++mt) {
#pragma unroll
        for (int nt = 0; nt < 4; ++nt) {
            int ncol = n0 + wn + nt * 8 + 2 * t4;
            float bx = __ldg(&bias[ncol]);
            float by = __ldg(&bias[ncol + 1]);
#pragma unroll
            for (int rr = 0; rr < 2; ++rr) {
                int m = m0 + wm + mt * 16 + g + rr * 8;
                float vx = acc[mt][nt][rr * 2] + bx;
                float vy = acc[mt][nt][rr * 2 + 1] + by;
                if (MODE == 0) {
                    int bb = m >> 11, ss = m & 2047;
                    int h = ncol / 192;
                    int rem = ncol - h * 192;
                    int part = rem >> 6;
                    int d = rem & 63;
                    size_t dst = (((size_t)(bb * H_ + h)) * S_ + ss) * HD_ + d;
                    float* dstp = (part == 0 ? g_Q : (part == 1 ? g_K : g_V));
                    dstp[dst] = vx;
                    dstp[dst + 1] = vy;
                } else {
                    *(float2*)&out[(size_t)m * D_ + ncol] = make_float2(vx, vy);
                }
            }
        }
    }
}

// ---------------------------------------------------------------------------
// Flash attention, tf32 mma. grid=(S/128, B*H), 256 threads.
// Double-buffered K/V smem + register prefetch, ONE barrier per k-tile.
// Q/K fragments via ldmatrix.x4; V scalar LDS (k-major frag layout).
// Base-2 softmax (ex2), stats in registers; bit-packed mask.
// ---------------------------------------------------------------------------
__global__ __launch_bounds__(256, 2) void attn_tc() {
    extern __shared__ unsigned sh[];
    unsigned* Qs = sh;                        // [128][68]
    unsigned* Ks = sh + 128 * 68;             // [2][64][68]
    unsigned* Vs = Ks + 2 * 64 * 68;          // [2][64][72]

    const int bh = blockIdx.y;
    const int q0 = blockIdx.x * 128;
    const int t = threadIdx.x;
    const int w = t >> 5;
    const int lane = t & 31;
    const int g = lane >> 2;
    const int t4 = lane & 3;

    const size_t base = (size_t)bh * (S_ * HD_);
    const float* Qg = g_Q + base;
    const float* Kg = g_K + base;
    const float* Vg = g_V + base;

    const int lrow = t >> 4;
    const int lseg = t & 15;

    // ldmatrix per-lane base offsets (words)
    const int lrow8 = lane & 7;
    const int msel = lane >> 3;
    const unsigned q_base = (w * 16 + ((msel & 1) << 3) + lrow8) * 68 + ((msel >> 1) << 2);
    const unsigned k_base = (((msel >> 1) << 3) + lrow8) * 68 + ((msel & 1) << 2);
    const unsigned sQ = smem_u32(Qs);
    const unsigned sK = smem_u32(Ks);

#pragma unroll
    for (int i = 0; i < 8; ++i) {
        int idx = t + i * 256;
        int row = idx >> 4, seg = idx & 15;
        float4 v = *(const float4*)(Qg + (size_t)(q0 + row) * HD_ + seg * 4);
        unsigned* p = &Qs[row * 68 + seg * 4];
        p[0] = f2tf(v.x); p[1] = f2tf(v.y); p[2] = f2tf(v.z); p[3] = f2tf(v.w);
    }

    float4 kr[4], vr[4];
#pragma unroll
    for (int i = 0; i < 4; ++i) {
        int row = lrow + i * 16;
        kr[i] = *(const float4*)(Kg + (size_t)row * HD_ + lseg * 4);
        vr[i] = *(const float4*)(Vg + (size_t)row * HD_ + lseg * 4);
    }
#pragma unroll
    for (int i = 0; i < 4; ++i) {
        int row = lrow + i * 16;
        unsigned* p = &Ks[row * 68 + lseg * 4];
        p[0] = f2tf(kr[i].x); p[1] = f2tf(kr[i].y); p[2] = f2tf(kr[i].z); p[3] = f2tf(kr[i].w);
        unsigned* q = &Vs[row * 72 + lseg * 4];
        q[0] = f2tf(vr[i].x); q[1] = f2tf(vr[i].y); q[2] = f2tf(vr[i].z); q[3] = f2tf(vr[i].w);
    }

    const int qrow0 = q0 + w * 16 + g;
    const int qrow1 = qrow0 + 8;
    const unsigned* mbp0 = g_Mb + (size_t)qrow0 * 64;
    const unsigned* mbp1 = g_Mb + (size_t)qrow1 * 64;

    float o[8][4];
#pragma unroll
    for (int nt = 0; nt < 8; ++nt)
#pragma unroll
        for (int i = 0; i < 4; ++i) o[nt][i] = 0.0f;
    float m0s = -INFINITY, m1s = -INFINITY, l0 = 0.0f, l1 = 0.0f;

    __syncthreads();

    for (int j = 0; j < 32; ++j) {
        const unsigned kbK = sK + (j & 1) * (64 * 68 * 4);
        const int kbV = (j & 1) * 64 * 72;
        if (j < 31) {
            const float* Kn = Kg + (size_t)(j + 1) * 64 * HD_;
            const float* Vn = Vg + (size_t)(j + 1) * 64 * HD_;
#pragma unroll
            for (int i = 0; i < 4; ++i) {
                int row = lrow + i * 16;
                kr[i] = *(const float4*)(Kn + (size_t)row * HD_ + lseg * 4);
                vr[i] = *(const float4*)(Vn + (size_t)row * HD_ + lseg * 4);
            }
        }
        uint2 mb0 = *(const uint2*)(mbp0 + j * 2);
        uint2 mb1 = *(const uint2*)(mbp1 + j * 2);

        // S = Q @ K^T  (Q frags + K frags via ldmatrix)
        float sc[8][4];
#pragma unroll
        for (int nt = 0; nt < 8; ++nt)
#pragma unroll
            for (int i = 0; i < 4; ++i) sc[nt][i] = 0.0f;
#pragma unroll
        for (int ks = 0; ks < 8; ++ks) {
            unsigned qa[4];
            ldsm4(qa, sQ + (q_base + ks * 8) * 4);
#pragma unroll
            for (int p = 0; p < 4; ++p) {
                unsigned kb4[4];
                ldsm4(kb4, kbK + (k_base + p * 16 * 68 + ks * 8) * 4);
                mma_tf32(sc[2 * p], qa[0], qa[1], qa[2], qa[3], kb4[0], kb4[1]);
                mma_tf32(sc[2 * p + 1], qa[0], qa[1], qa[2], qa[3], kb4[2], kb4[3]);
            }
        }

#pragma unroll
        for (int nt = 0; nt < 8; ++nt) {
            unsigned w0 = (nt < 4) ? mb0.x : mb0.y;
            unsigned w1 = (nt < 4) ? mb1.x : mb1.y;
            int shv = (nt & 3) * 8 + 2 * t4;
            unsigned b0 = w0 >> shv;
            unsigned b1 = w1 >> shv;
            sc[nt][0] = (b0 & 1) ? sc[nt][0] * SCALE2 : NEGINF;
            sc[nt][1] = (b0 & 2) ? sc[nt][1] * SCALE2 : NEGINF;
            sc[nt][2] = (b1 & 1) ? sc[nt][2] * SCALE2 : NEGINF;
            sc[nt][3] = (b1 & 2) ? sc[nt][3] * SCALE2 : NEGINF;
        }

        float mx0 = -INFINITY, mx1 = -INFINITY;
#pragma unroll
        for (int nt = 0; nt < 8; ++nt) {
            mx0 = fmaxf(mx0, fmaxf(sc[nt][0], sc[nt][1]));
            mx1 = fmaxf(mx1, fmaxf(sc[nt][2], sc[nt][3]));
        }
        mx0 = fmaxf(mx0, __shfl_xor_sync(0xffffffffu, mx0, 1));
        mx0 = fmaxf(mx0, __shfl_xor_sync(0xffffffffu, mx0, 2));
        mx1 = fmaxf(mx1, __shfl_xor_sync(0xffffffffu, mx1, 1));
        mx1 = fmaxf(mx1, __shfl_xor_sync(0xffffffffu, mx1, 2));
        float mn0 = fmaxf(m0s, mx0), mn1 = fmaxf(m1s, mx1);
        float al0 = ex2(m0s - mn0), al1 = ex2(m1s - mn1);
        m0s = mn0; m1s = mn1;
        float rs0 = 0.0f, rs1 = 0.0f;
#pragma unroll
        for (int nt = 0; nt < 8; ++nt) {
            sc[nt][0] = ex2(sc[nt][0] - mn0);
            sc[nt][1] = ex2(sc[nt][1] - mn0);
            sc[nt][2] = ex2(sc[nt][2] - mn1);
            sc[nt][3] = ex2(sc[nt][3] - mn1);
            rs0 += sc[nt][0] + sc[nt][1];
            rs1 += sc[nt][2] + sc[nt][3];
        }
        rs0 += __shfl_xor_sync(0xffffffffu, rs0, 1);
        rs0 += __shfl_xor_sync(0xffffffffu, rs0, 2);
        rs1 += __shfl_xor_sync(0xffffffffu, rs1, 1);
        rs1 += __shfl_xor_sync(0xffffffffu, rs1, 2);
        l0 = al0 * l0 + rs0;
        l1 = al1 * l1 + rs1;
#pragma unroll
        for (int nt = 0; nt < 8; ++nt) {
            o[nt][0] *= al0; o[nt][1] *= al0;
            o[nt][2] *= al1; o[nt][3] *= al1;
        }

        // O += P @ V : relayout P C-frag -> A-frag via shfl
        const int s0l = (lane & ~3) | (t4 >> 1);
        const int s1l = s0l + 2;
        const bool odd = (t4 & 1);
#pragma unroll
        for (int kt = 0; kt < 8; ++kt) {
            float e00 = __shfl_sync(0xffffffffu, sc[kt][0], s0l);
            float e01 = __shfl_sync(0xffffffffu, sc[kt][1], s0l);
            float e10 = __shfl_sync(0xffffffffu, sc[kt][2], s0l);
            float e11 = __shfl_sync(0xffffffffu, sc[kt][3], s0l);
            float f00 = __shfl_sync(0xffffffffu, sc[kt][0], s1l);
            float f01 = __shfl_sync(0xffffffffu, sc[kt][1], s1l);
            float f10 = __shfl_sync(0xffffffffu, sc[kt][2], s1l);
            float f11 = __shfl_sync(0xffffffffu, sc[kt][3], s1l);
            unsigned a0 = f2tf(odd ? e01 : e00);
            unsigned a1 = f2tf(odd ? e11 : e10);
            unsigned a2 = f2tf(odd ? f01 : f00);
            unsigned a3 = f2tf(odd ? f11 : f10);
#pragma unroll
            for (int nt = 0; nt < 8; ++nt) {
                unsigned b0 = Vs[kbV + (kt * 8 + t4) * 72 + nt * 8 + g];
                unsigned b1 = Vs[kbV + (kt * 8 + t4 + 4) * 72 + nt * 8 + g];
                mma_tf32(o[nt], a0, a1, a2, a3, b0, b1);
            }
        }

        if (j < 31) {
            const int nbK = ((j + 1) & 1) * 64 * 68;
            const int nbV = ((j + 1) & 1) * 64 * 72;
#pragma unroll
            for (int i = 0; i < 4; ++i) {
                int row = lrow + i * 16;
                unsigned* p = &Ks[nbK + row * 68 + lseg * 4];
                p[0] = f2tf(kr[i].x); p[1] = f2tf(kr[i].y);
                p[2] = f2tf(kr[i].z); p[3] = f2tf(kr[i].w);
                unsigned* q = &Vs[nbV + row * 72 + lseg * 4];
                q[0] = f2tf(vr[i].x); q[1] = f2tf(vr[i].y);
                q[2] = f2tf(vr[i].z); q[3] = f2tf(vr[i].w);
            }
        }
        __syncthreads();
    }

    const int bb = bh >> 4;
    const int h = bh & 15;
    float inv0 = 1.0f / l0, inv1 = 1.0f / l1;
#pragma unroll
    for (int nt = 0; nt < 8; ++nt) {
        int dcol = h * 64 + nt * 8 + 2 * t4;
        size_t r0 = ((size_t)bb * S_ + qrow0) * D_ + dcol;
        size_t r1 = ((size_t)bb * S_ + qrow1) * D_ + dcol;
        *(float2*)&g_C[r0] = make_float2(o[nt][0] * inv0, o[nt][1] * inv0);
        *(float2*)&g_C[r1] = make_float2(o[nt][2] * inv1, o[nt][3] * inv1);
    }
}

// ---------------------------------------------------------------------------
extern "C" void kernel_launch(void* const* d_in, const int* in_sizes, int n_in,
                              void* d_out, int out_size) {
    const float* x     = (const float*)d_in[0];
    const int*   mask  = (const int*)d_in[1];
    const float* w_qkv = (const float*)d_in[2];
    const float* b_qkv = (const float*)d_in[3];
    const float* w_o   = (const float*)d_in[4];
    const float* b_o   = (const float*)d_in[5];
    float* out = (float*)d_out;

    const int gemm_smem = 4 * 128 * 36 * (int)sizeof(unsigned);               // 73728
    const int attn_smem = (128 * 68 + 2 * 64 * 68 + 2 * 64 * 72) * (int)sizeof(unsigned); // 106496

    cudaFuncSetAttribute(gemm_tc<0>, cudaFuncAttributeMaxDynamicSharedMemorySize, gemm_smem);
    cudaFuncSetAttribute(gemm_tc<1>, cudaFuncAttributeMaxDynamicSharedMemorySize, gemm_smem);
    cudaFuncSetAttribute(attn_tc, cudaFuncAttributeMaxDynamicSharedMemorySize, attn_smem);

    // 0) pack mask bits
    maskpack<<<S_ * (S_ / 32) / 256, 256>>>(mask);

    // 1) QKV projection
    gemm_tc<0><<<dim3(3072 / 128, 4096 / 128), 256, gemm_smem>>>(x, w_qkv, b_qkv, nullptr);

    // 2) flash attention
    attn_tc<<<dim3(S_ / 128, B_ * H_), 256, attn_smem>>>();

    // 3) output projection
    gemm_tc<1><<<dim3(1024 / 128, 4096 / 128), 256, gemm_smem>>>(nullptr, w_o, b_o, out);
}

// round 9
// speedup vs baseline: 20.6354x; 1.1954x over previous
#include <cuda_runtime.h>
#include <cuda_fp16.h>
#include <math.h>
#include <cstdint>

#define B_ 2
#define S_ 2048
#define D_ 1024
#define H_ 16
#define HD_ 64
#define NEGINF (-9000000000000000.0f)
#define SCALE2 0.1803368801111204f

// Scratch (device globals: allocation-free rule)
__device__ __half g_Qh[B_ * H_ * S_ * HD_];
__device__ __half g_Kh[B_ * H_ * S_ * HD_];
__device__ __half g_Vh[B_ * H_ * S_ * HD_];
__device__ __half g_Ch[B_ * S_ * D_];
__device__ __half g_Xh[B_ * S_ * D_];
__device__ __half g_W1h[3 * D_ * D_];
__device__ __half g_W2h[D_ * D_];
__device__ unsigned g_Mb[S_ * (S_ / 32)];

__device__ __forceinline__ float ex2(float x) {
    float y;
    asm("ex2.approx.f32 %0, %1;" : "=f"(y) : "f"(x));
    return y;
}
__device__ __forceinline__ unsigned h2(float a, float b) {
    __half2 h = __floats2half2_rn(a, b);
    return *(unsigned*)&h;
}
__device__ __forceinline__ void mma_f16(float c[4], unsigned a0, unsigned a1,
                                        unsigned a2, unsigned a3,
                                        unsigned b0, unsigned b1) {
    asm volatile(
        "mma.sync.aligned.m16n8k16.row.col.f32.f16.f16.f32 "
        "{%0,%1,%2,%3}, {%4,%5,%6,%7}, {%8,%9}, {%0,%1,%2,%3};"
        : "+f"(c[0]), "+f"(c[1]), "+f"(c[2]), "+f"(c[3])
        : "r"(a0), "r"(a1), "r"(a2), "r"(a3), "r"(b0), "r"(b1));
}
__device__ __forceinline__ unsigned smem_u32(const void* p) {
    return (unsigned)__cvta_generic_to_shared(p);
}
__device__ __forceinline__ void ldsm4(unsigned r[4], unsigned addr) {
    asm volatile(
        "ldmatrix.sync.aligned.m8n8.x4.shared.b16 {%0,%1,%2,%3}, [%4];"
        : "=r"(r[0]), "=r"(r[1]), "=r"(r[2]), "=r"(r[3]) : "r"(addr));
}
__device__ __forceinline__ void ldsm4t(unsigned r[4], unsigned addr) {
    asm volatile(
        "ldmatrix.sync.aligned.m8n8.x4.trans.shared.b16 {%0,%1,%2,%3}, [%4];"
        : "=r"(r[0]), "=r"(r[1]), "=r"(r[2]), "=r"(r[3]) : "r"(addr));
}

// ---------------------------------------------------------------------------
__global__ __launch_bounds__(256) void maskpack(const int* __restrict__ mask) {
    int idx = blockIdx.x * 256 + threadIdx.x;
    int r = idx >> 6, wc = idx & 63;
    const int4* p = (const int4*)(mask + (size_t)r * S_ + wc * 32);
    unsigned bits = 0;
#pragma unroll
    for (int i = 0; i < 8; ++i) {
        int4 m = __ldg(p + i);
        bits |= (unsigned)(m.x != 0) << (4 * i)
              | (unsigned)(m.y != 0) << (4 * i + 1)
              | (unsigned)(m.z != 0) << (4 * i + 2)
              | (unsigned)(m.w != 0) << (4 * i + 3);
    }
    g_Mb[idx] = bits;
}

// f32 -> f16 bulk convert (one-time, 8 elems/thread)
__global__ __launch_bounds__(256) void conv_h(const float* __restrict__ in,
                                              __half* __restrict__ outp) {
    int i = (blockIdx.x * 256 + threadIdx.x) * 8;
    float4 v0 = *(const float4*)(in + i);
    float4 v1 = *(const float4*)(in + i + 4);
    uint4 u;
    u.x = h2(v0.x, v0.y); u.y = h2(v0.z, v0.w);
    u.z = h2(v1.x, v1.y); u.w = h2(v1.z, v1.w);
    *(uint4*)(outp + i) = u;
}

// ---------------------------------------------------------------------------
// fp16 tensor-core GEMM: C[M,N] = A[M,1024] @ W[N,1024]^T + bias (f32 accum)
// Block 128x128, BK=64 halves, double-buffered, register prefetch, ONE
// barrier/iter. 8 warps (2x4), warp tile 64x32. Row stride 72 halves (144B):
// bankquad = (row+seg)&7 -> conflict-free STS.128 and LDSM phases.
// MODE 0: A=g_Xh, N=3072, scatter half2 into g_Qh/g_Kh/g_Vh.
// MODE 1: A=g_Ch, N=1024, out f32.
// ---------------------------------------------------------------------------
template <int MODE>
__global__ __launch_bounds__(256, 2) void gemm_tc(const __half* __restrict__ A,
                                                  const __half* __restrict__ W,
                                                  const float* __restrict__ bias,
                                                  float* __restrict__ out) {
    extern __shared__ __half shh[];
    __half* As = shh;                  // [2][128][72]
    __half* Bs = shh + 2 * 128 * 72;   // [2][128][72]

    const int m0 = blockIdx.y * 128;
    const int n0 = blockIdx.x * 128;
    const int t = threadIdx.x;
    const int w = t >> 5;
    const int lane = t & 31;
    const int g = lane >> 2;
    const int t4 = lane & 3;
    const int wm = (w >> 2) * 64;
    const int wn = (w & 3) * 32;

    const int seg = t & 7;        // 0..7 (8 halves each)
    const int r0 = t >> 3;        // 0..31

    const unsigned sA = smem_u32(As);
    const unsigned sB = smem_u32(Bs);
    const unsigned BUF = 128 * 72 * 2;  // bytes per buffer
    // ldmatrix per-lane byte offsets within a buffer
    const unsigned aoff = (wm + (lane & 15)) * 144 + (lane >> 4) * 16;
    const unsigned boff = (wn + (lane & 15)) * 144 + (lane >> 4) * 16;

    uint4 ar[4], br[4];
#pragma unroll
    for (int i = 0; i < 4; ++i) {
        int row = r0 + i * 32;
        ar[i] = *(const uint4*)(A + (size_t)(m0 + row) * D_ + seg * 8);
        br[i] = *(const uint4*)(W + (size_t)(n0 + row) * D_ + seg * 8);
    }
#pragma unroll
    for (int i = 0; i < 4; ++i) {
        int row = r0 + i * 32;
        *(uint4*)&As[row * 72 + seg * 8] = ar[i];
        *(uint4*)&Bs[row * 72 + seg * 8] = br[i];
    }
    __syncthreads();

    float acc[4][4][4];
#pragma unroll
    for (int mt = 0; mt < 4; ++mt)
#pragma unroll
        for (int nt = 0; nt < 4; ++nt)
#pragma unroll
            for (int i = 0; i < 4; ++i) acc[mt][nt][i] = 0.0f;

    for (int k0 = 0; k0 < 16; ++k0) {
        const unsigned bA = sA + (k0 & 1) * BUF;
        const unsigned bB = sB + (k0 & 1) * BUF;
        if (k0 < 15) {
            int ko = (k0 + 1) * 64;
#pragma unroll
            for (int i = 0; i < 4; ++i) {
                int row = r0 + i * 32;
                ar[i] = *(const uint4*)(A + (size_t)(m0 + row) * D_ + ko + seg * 8);
                br[i] = *(const uint4*)(W + (size_t)(n0 + row) * D_ + ko + seg * 8);
            }
        }
#pragma unroll
        for (int ks = 0; ks < 4; ++ks) {
            unsigned a[4][4];
#pragma unroll
            for (int mt = 0; mt < 4; ++mt)
                ldsm4(a[mt], bA + aoff + mt * 16 * 144 + ks * 32);
#pragma unroll
            for (int p = 0; p < 2; ++p) {
                unsigned bb[4];
                ldsm4(bb, bB + boff + p * 16 * 144 + ks * 32);
#pragma unroll
                for (int mt = 0; mt < 4; ++mt) {
                    mma_f16(acc[mt][2 * p], a[mt][0], a[mt][1], a[mt][2], a[mt][3],
                            bb[0], bb[2]);
                    mma_f16(acc[mt][2 * p + 1], a[mt][0], a[mt][1], a[mt][2], a[mt][3],
                            bb[1], bb[3]);
                }
            }
        }
        if (k0 < 15) {
            __half* Ad = As + ((k0 + 1) & 1) * 128 * 72;
            __half* Bd = Bs + ((k0 + 1) & 1) * 128 * 72;
#pragma unroll
            for (int i = 0; i < 4; ++i) {
                int row = r0 + i * 32;
                *(uint4*)&Ad[row * 72 + seg * 8] = ar[i];
                *(uint4*)&Bd[row * 72 + seg * 8] = br[i];
            }
        }
        __syncthreads();
    }

    // epilogue
#pragma unroll
    for (int mt = 0; mt < 4; ++mt) {
#pragma unroll
        for (int nt = 0; nt < 4; ++nt) {
            int ncol = n0 + wn + nt * 8 + 2 * t4;
            float bx = __ldg(&bias[ncol]);
            float by = __ldg(&bias[ncol + 1]);
#pragma unroll
            for (int rr = 0; rr < 2; ++rr) {
                int m = m0 + wm + mt * 16 + g + rr * 8;
                float vx = acc[mt][nt][rr * 2] + bx;
                float vy = acc[mt][nt][rr * 2 + 1] + by;
                if (MODE == 0) {
                    int bb2 = m >> 11, ss = m & 2047;
                    int h = ncol / 192;
                    int rem = ncol - h * 192;
                    int part = rem >> 6;
                    int d = rem & 63;
                    size_t dst = (((size_t)(bb2 * H_ + h)) * S_ + ss) * HD_ + d;
                    __half* dstp = (part == 0 ? g_Qh : (part == 1 ? g_Kh : g_Vh));
                    __half2 hv = __floats2half2_rn(vx, vy);
                    *(__half2*)&dstp[dst] = hv;
                } else {
                    *(float2*)&out[(size_t)m * D_ + ncol] = make_float2(vx, vy);
                }
            }
        }
    }
}

// ---------------------------------------------------------------------------
// Flash attention, fp16 mma m16n8k16. grid=(S/128, B*H), 256 threads.
// Double-buffered K/V + register prefetch, ONE barrier/j-tile.
// Q/K frags via ldmatrix.x4; V via ldmatrix.x4.trans (FA2 recipe).
// P stays in registers: fp16 A-frag k-pairs == QK^T C-frag col-pairs.
// Base-2 softmax in f32; bit-packed mask.
// ---------------------------------------------------------------------------
__global__ __launch_bounds__(256, 2) void attn_tc() {
    extern __shared__ __half shh[];
    __half* Qs = shh;                   // [128][72]
    __half* Ks = shh + 128 * 72;        // [2][64][72]
    __half* Vs = Ks + 2 * 64 * 72;      // [2][64][72]

    const int bh = blockIdx.y;
    const int q0 = blockIdx.x * 128;
    const int t = threadIdx.x;
    const int w = t >> 5;
    const int lane = t & 31;
    const int g = lane >> 2;
    const int t4 = lane & 3;

    const size_t base = (size_t)bh * (S_ * HD_);
    const __half* Qg = g_Qh + base;
    const __half* Kg = g_Kh + base;
    const __half* Vg = g_Vh + base;

    const int seg = t & 7;
    const int r0 = t >> 3;   // 0..31

    const unsigned sQ = smem_u32(Qs);
    const unsigned sK = smem_u32(Ks);
    const unsigned sV = smem_u32(Vs);
    const unsigned KBUF = 64 * 72 * 2;
    const unsigned qoff = (w * 16 + (lane & 15)) * 144 + (lane >> 4) * 16;
    const unsigned koff = (lane & 15) * 144 + (lane >> 4) * 16;
    const unsigned voff = (lane & 15) * 144 + (lane >> 4) * 16;

    // stage Q (128x64 halves)
#pragma unroll
    for (int i = 0; i < 4; ++i) {
        int row = r0 + i * 32;
        *(uint4*)&Qs[row * 72 + seg * 8] =
            *(const uint4*)(Qg + (size_t)(q0 + row) * HD_ + seg * 8);
    }
    // stage K/V tile 0
    uint4 kr[2], vr[2];
#pragma unroll
    for (int i = 0; i < 2; ++i) {
        int row = r0 + i * 32;
        kr[i] = *(const uint4*)(Kg + (size_t)row * HD_ + seg * 8);
        vr[i] = *(const uint4*)(Vg + (size_t)row * HD_ + seg * 8);
    }
#pragma unroll
    for (int i = 0; i < 2; ++i) {
        int row = r0 + i * 32;
        *(uint4*)&Ks[row * 72 + seg * 8] = kr[i];
        *(uint4*)&Vs[row * 72 + seg * 8] = vr[i];
    }

    const int qrow0 = q0 + w * 16 + g;
    const int qrow1 = qrow0 + 8;
    const unsigned* mbp0 = g_Mb + (size_t)qrow0 * 64;
    const unsigned* mbp1 = g_Mb + (size_t)qrow1 * 64;

    float o[8][4];
#pragma unroll
    for (int nt = 0; nt < 8; ++nt)
#pragma unroll
        for (int i = 0; i < 4; ++i) o[nt][i] = 0.0f;
    float m0s = -INFINITY, m1s = -INFINITY, l0 = 0.0f, l1 = 0.0f;

    __syncthreads();

    for (int j = 0; j < 32; ++j) {
        const unsigned bK = sK + (j & 1) * KBUF;
        const unsigned bV = sV + (j & 1) * KBUF;
        if (j < 31) {
            const __half* Kn = Kg + (size_t)(j + 1) * 64 * HD_;
            const __half* Vn = Vg + (size_t)(j + 1) * 64 * HD_;
#pragma unroll
            for (int i = 0; i < 2; ++i) {
                int row = r0 + i * 32;
                kr[i] = *(const uint4*)(Kn + (size_t)row * HD_ + seg * 8);
                vr[i] = *(const uint4*)(Vn + (size_t)row * HD_ + seg * 8);
            }
        }
        uint2 mb0 = *(const uint2*)(mbp0 + j * 2);
        uint2 mb1 = *(const uint2*)(mbp1 + j * 2);

        // S = Q @ K^T  (4 k16 steps over hd=64)
        float sc[8][4];
#pragma unroll
        for (int nt = 0; nt < 8; ++nt)
#pragma unroll
            for (int i = 0; i < 4; ++i) sc[nt][i] = 0.0f;
#pragma unroll
        for (int ks = 0; ks < 4; ++ks) {
            unsigned qa[4];
            ldsm4(qa, sQ + qoff + ks * 32);
#pragma unroll
            for (int p = 0; p < 4; ++p) {
                unsigned kb[4];
                ldsm4(kb, bK + koff + p * 16 * 144 + ks * 32);
                mma_f16(sc[2 * p], qa[0], qa[1], qa[2], qa[3], kb[0], kb[2]);
                mma_f16(sc[2 * p + 1], qa[0], qa[1], qa[2], qa[3], kb[1], kb[3]);
            }
        }

        // scale (base-2) + mask bits
#pragma unroll
        for (int nt = 0; nt < 8; ++nt) {
            unsigned w0 = (nt < 4) ? mb0.x : mb0.y;
            unsigned w1 = (nt < 4) ? mb1.x : mb1.y;
            int shv = (nt & 3) * 8 + 2 * t4;
            unsigned b0 = w0 >> shv;
            unsigned b1 = w1 >> shv;
            sc[nt][0] = (b0 & 1) ? sc[nt][0] * SCALE2 : NEGINF;
            sc[nt][1] = (b0 & 2) ? sc[nt][1] * SCALE2 : NEGINF;
            sc[nt][2] = (b1 & 1) ? sc[nt][2] * SCALE2 : NEGINF;
            sc[nt][3] = (b1 & 2) ? sc[nt][3] * SCALE2 : NEGINF;
        }

        // online softmax (f32, register stats)
        float mx0 = -INFINITY, mx1 = -INFINITY;
#pragma unroll
        for (int nt = 0; nt < 8; ++nt) {
            mx0 = fmaxf(mx0, fmaxf(sc[nt][0], sc[nt][1]));
            mx1 = fmaxf(mx1, fmaxf(sc[nt][2], sc[nt][3]));
        }
        mx0 = fmaxf(mx0, __shfl_xor_sync(0xffffffffu, mx0, 1));
        mx0 = fmaxf(mx0, __shfl_xor_sync(0xffffffffu, mx0, 2));
        mx1 = fmaxf(mx1, __shfl_xor_sync(0xffffffffu, mx1, 1));
        mx1 = fmaxf(mx1, __shfl_xor_sync(0xffffffffu, mx1, 2));
        float mn0 = fmaxf(m0s, mx0), mn1 = fmaxf(m1s, mx1);
        float al0 = ex2(m0s - mn0), al1 = ex2(m1s - mn1);
        m0s = mn0; m1s = mn1;
        float rs0 = 0.0f, rs1 = 0.0f;
#pragma unroll
        for (int nt = 0; nt < 8; ++nt) {
            sc[nt][0] = ex2(sc[nt][0] - mn0);
            sc[nt][1] = ex2(sc[nt][1] - mn0);
            sc[nt][2] = ex2(sc[nt][2] - mn1);
            sc[nt][3] = ex2(sc[nt][3] - mn1);
            rs0 += sc[nt][0] + sc[nt][1];
            rs1 += sc[nt][2] + sc[nt][3];
        }
        rs0 += __shfl_xor_sync(0xffffffffu, rs0, 1);
        rs0 += __shfl_xor_sync(0xffffffffu, rs0, 2);
        rs1 += __shfl_xor_sync(0xffffffffu, rs1, 1);
        rs1 += __shfl_xor_sync(0xffffffffu, rs1, 2);
        l0 = al0 * l0 + rs0;
        l1 = al1 * l1 + rs1;
#pragma unroll
        for (int nt = 0; nt < 8; ++nt) {
            o[nt][0] *= al0; o[nt][1] *= al0;
            o[nt][2] *= al1; o[nt][3] *= al1;
        }

        // O += P @ V : P packs straight from sc (no shuffle), V via ldsm.trans
#pragma unroll
        for (int kt = 0; kt < 4; ++kt) {
            unsigned a0 = h2(sc[2 * kt][0], sc[2 * kt][1]);
            unsigned a1 = h2(sc[2 * kt][2], sc[2 * kt][3]);
            unsigned a2 = h2(sc[2 * kt + 1][0], sc[2 * kt + 1][1]);
            unsigned a3 = h2(sc[2 * kt + 1][2], sc[2 * kt + 1][3]);
#pragma unroll
            for (int q = 0; q < 4; ++q) {
                unsigned vb[4];
                ldsm4t(vb, bV + voff + kt * 16 * 144 + q * 32);
                mma_f16(o[2 * q], a0, a1, a2, a3, vb[0], vb[1]);
                mma_f16(o[2 * q + 1], a0, a1, a2, a3, vb[2], vb[3]);
            }
        }

        if (j < 31) {
            __half* Kd = Ks + ((j + 1) & 1) * 64 * 72;
            __half* Vd = Vs + ((j + 1) & 1) * 64 * 72;
#pragma unroll
            for (int i = 0; i < 2; ++i) {
                int row = r0 + i * 32;
                *(uint4*)&Kd[row * 72 + seg * 8] = kr[i];
                *(uint4*)&Vd[row * 72 + seg * 8] = vr[i];
            }
        }
        __syncthreads();
    }

    // epilogue: normalize, write half2 ctx
    const int bb = bh >> 4;
    const int h = bh & 15;
    float inv0 = 1.0f / l0, inv1 = 1.0f / l1;
#pragma unroll
    for (int nt = 0; nt < 8; ++nt) {
        int dcol = h * 64 + nt * 8 + 2 * t4;
        size_t rr0 = ((size_t)bb * S_ + qrow0) * D_ + dcol;
        size_t rr1 = ((size_t)bb * S_ + qrow1) * D_ + dcol;
        __half2 v0 = __floats2half2_rn(o[nt][0] * inv0, o[nt][1] * inv0);
        __half2 v1 = __floats2half2_rn(o[nt][2] * inv1, o[nt][3] * inv1);
        *(__half2*)&g_Ch[rr0] = v0;
        *(__half2*)&g_Ch[rr1] = v1;
    }
}

// ---------------------------------------------------------------------------
extern "C" void kernel_launch(void* const* d_in, const int* in_sizes, int n_in,
                              void* d_out, int out_size) {
    const float* x     = (const float*)d_in[0];
    const int*   mask  = (const int*)d_in[1];
    const float* w_qkv = (const float*)d_in[2];
    const float* b_qkv = (const float*)d_in[3];
    const float* w_o   = (const float*)d_in[4];
    const float* b_o   = (const float*)d_in[5];
    float* out = (float*)d_out;

    const int gemm_smem = 4 * 128 * 72 * 2;                     // 73728
    const int attn_smem = (128 * 72 + 4 * 64 * 72) * 2;         // 55296

    cudaFuncSetAttribute(gemm_tc<0>, cudaFuncAttributeMaxDynamicSharedMemorySize, gemm_smem);
    cudaFuncSetAttribute(gemm_tc<1>, cudaFuncAttributeMaxDynamicSharedMemorySize, gemm_smem);
    cudaFuncSetAttribute(attn_tc, cudaFuncAttributeMaxDynamicSharedMemorySize, attn_smem);

    // 0) one-time prep
    maskpack<<<S_ * (S_ / 32) / 256, 256>>>(mask);
    __half *dXh, *dW1h, *dW2h, *dCh;
    cudaGetSymbolAddress((void**)&dXh, g_Xh);
    cudaGetSymbolAddress((void**)&dW1h, g_W1h);
    cudaGetSymbolAddress((void**)&dW2h, g_W2h);
    cudaGetSymbolAddress((void**)&dCh, g_Ch);
    conv_h<<<B_ * S_ * D_ / 2048, 256>>>(x, dXh);
    conv_h<<<3 * D_ * D_ / 2048, 256>>>(w_qkv, dW1h);
    conv_h<<<D_ * D_ / 2048, 256>>>(w_o, dW2h);

    // 1) QKV projection
    gemm_tc<0><<<dim3(3072 / 128, 4096 / 128), 256, gemm_smem>>>(dXh, dW1h, b_qkv, nullptr);

    // 2) flash attention
    attn_tc<<<dim3(S_ / 128, B_ * H_), 256, attn_smem>>>();

    // 3) output projection
    gemm_tc<1><<<dim3(1024 / 128, 4096 / 128), 256, gemm_smem>>>(dCh, dW2h, b_o, out);
}

// round 10
// speedup vs baseline: 29.2123x; 1.4156x over previous
#include <cuda_runtime.h>
#include <cuda_fp16.h>
#include <math.h>
#include <cstdint>

#define B_ 2
#define S_ 2048
#define D_ 1024
#define H_ 16
#define HD_ 64
#define SCALE2 0.1803368801111204f
#define ONESH2 0x3C003C00u

// Scratch (device globals: allocation-free rule)
__device__ __half g_Qh[B_ * H_ * S_ * HD_];
__device__ __half g_Kh[B_ * H_ * S_ * HD_];
__device__ __half g_Vh[B_ * H_ * S_ * HD_];
__device__ __half g_Ch[B_ * S_ * D_];
__device__ __half g_Xh[B_ * S_ * D_];
__device__ __half g_W1h[3 * D_ * D_];
__device__ __half g_W2h[D_ * D_];
__device__ __half g_Bh[S_ * S_];   // additive mask bias: 0 or -32768

__device__ __forceinline__ float ex2(float x) {
    float y;
    asm("ex2.approx.f32 %0, %1;" : "=f"(y) : "f"(x));
    return y;
}
__device__ __forceinline__ unsigned ex2h2(unsigned x) {
    unsigned y;
    asm("ex2.approx.f16x2 %0, %1;" : "=r"(y) : "r"(x));
    return y;
}
__device__ __forceinline__ unsigned h2(float a, float b) {
    __half2 h = __floats2half2_rn(a, b);
    return *(unsigned*)&h;
}
__device__ __forceinline__ unsigned hadd2u(unsigned a, unsigned b) {
    __half2 r = __hadd2(*(__half2*)&a, *(__half2*)&b);
    return *(unsigned*)&r;
}
__device__ __forceinline__ void mma_f16(float c[4], unsigned a0, unsigned a1,
                                        unsigned a2, unsigned a3,
                                        unsigned b0, unsigned b1) {
    asm volatile(
        "mma.sync.aligned.m16n8k16.row.col.f32.f16.f16.f32 "
        "{%0,%1,%2,%3}, {%4,%5,%6,%7}, {%8,%9}, {%0,%1,%2,%3};"
        : "+f"(c[0]), "+f"(c[1]), "+f"(c[2]), "+f"(c[3])
        : "r"(a0), "r"(a1), "r"(a2), "r"(a3), "r"(b0), "r"(b1));
}
__device__ __forceinline__ unsigned smem_u32(const void* p) {
    return (unsigned)__cvta_generic_to_shared(p);
}
__device__ __forceinline__ void ldsm4(unsigned r[4], unsigned addr) {
    asm volatile(
        "ldmatrix.sync.aligned.m8n8.x4.shared.b16 {%0,%1,%2,%3}, [%4];"
        : "=r"(r[0]), "=r"(r[1]), "=r"(r[2]), "=r"(r[3]) : "r"(addr));
}
__device__ __forceinline__ void ldsm4t(unsigned r[4], unsigned addr) {
    asm volatile(
        "ldmatrix.sync.aligned.m8n8.x4.trans.shared.b16 {%0,%1,%2,%3}, [%4];"
        : "=r"(r[0]), "=r"(r[1]), "=r"(r[2]), "=r"(r[3]) : "r"(addr));
}

// ---------------------------------------------------------------------------
// Expand int mask -> additive fp16 bias (0 or -32768). 8 elems/thread.
__global__ __launch_bounds__(256) void biasprep(const int* __restrict__ mask) {
    int i = (blockIdx.x * 256 + threadIdx.x) * 8;
    int4 m0 = __ldg((const int4*)(mask + i));
    int4 m1 = __ldg((const int4*)(mask + i + 4));
    uint4 u;
    u.x = (m0.x ? 0u : 0xF800u) | (m0.y ? 0u : 0xF8000000u);
    u.y = (m0.z ? 0u : 0xF800u) | (m0.w ? 0u : 0xF8000000u);
    u.z = (m1.x ? 0u : 0xF800u) | (m1.y ? 0u : 0xF8000000u);
    u.w = (m1.z ? 0u : 0xF800u) | (m1.w ? 0u : 0xF8000000u);
    *(uint4*)((__half*)g_Bh + i) = u;
}

// f32 -> f16 bulk convert (one-time, 8 elems/thread)
__global__ __launch_bounds__(256) void conv_h(const float* __restrict__ in,
                                              __half* __restrict__ outp) {
    int i = (blockIdx.x * 256 + threadIdx.x) * 8;
    float4 v0 = *(const float4*)(in + i);
    float4 v1 = *(const float4*)(in + i + 4);
    uint4 u;
    u.x = h2(v0.x, v0.y); u.y = h2(v0.z, v0.w);
    u.z = h2(v1.x, v1.y); u.w = h2(v1.z, v1.w);
    *(uint4*)(outp + i) = u;
}

// ---------------------------------------------------------------------------
// fp16 tensor-core GEMM (unchanged from round 9, except MODE 0 pre-scales Q
// by SCALE2 so attention logits come out of QK^T already in base-2 domain).
// ---------------------------------------------------------------------------
template <int MODE>
__global__ __launch_bounds__(256, 2) void gemm_tc(const __half* __restrict__ A,
                                                  const __half* __restrict__ W,
                                                  const float* __restrict__ bias,
                                                  float* __restrict__ out) {
    extern __shared__ __half shh[];
    __half* As = shh;                  // [2][128][72]
    __half* Bs = shh + 2 * 128 * 72;   // [2][128][72]

    const int m0 = blockIdx.y * 128;
    const int n0 = blockIdx.x * 128;
    const int t = threadIdx.x;
    const int w = t >> 5;
    const int lane = t & 31;
    const int g = lane >> 2;
    const int t4 = lane & 3;
    const int wm = (w >> 2) * 64;
    const int wn = (w & 3) * 32;

    const int seg = t & 7;
    const int r0 = t >> 3;

    const unsigned sA = smem_u32(As);
    const unsigned sB = smem_u32(Bs);
    const unsigned BUF = 128 * 72 * 2;
    const unsigned aoff = (wm + (lane & 15)) * 144 + (lane >> 4) * 16;
    const unsigned boff = (wn + (lane & 15)) * 144 + (lane >> 4) * 16;

    uint4 ar[4], br[4];
#pragma unroll
    for (int i = 0; i < 4; ++i) {
        int row = r0 + i * 32;
        ar[i] = *(const uint4*)(A + (size_t)(m0 + row) * D_ + seg * 8);
        br[i] = *(const uint4*)(W + (size_t)(n0 + row) * D_ + seg * 8);
    }
#pragma unroll
    for (int i = 0; i < 4; ++i) {
        int row = r0 + i * 32;
        *(uint4*)&As[row * 72 + seg * 8] = ar[i];
        *(uint4*)&Bs[row * 72 + seg * 8] = br[i];
    }
    __syncthreads();

    float acc[4][4][4];
#pragma unroll
    for (int mt = 0; mt < 4; ++mt)
#pragma unroll
        for (int nt = 0; nt < 4; ++nt)
#pragma unroll
            for (int i = 0; i < 4; ++i) acc[mt][nt][i] = 0.0f;

    for (int k0 = 0; k0 < 16; ++k0) {
        const unsigned bA = sA + (k0 & 1) * BUF;
        const unsigned bB = sB + (k0 & 1) * BUF;
        if (k0 < 15) {
            int ko = (k0 + 1) * 64;
#pragma unroll
            for (int i = 0; i < 4; ++i) {
                int row = r0 + i * 32;
                ar[i] = *(const uint4*)(A + (size_t)(m0 + row) * D_ + ko + seg * 8);
                br[i] = *(const uint4*)(W + (size_t)(n0 + row) * D_ + ko + seg * 8);
            }
        }
#pragma unroll
        for (int ks = 0; ks < 4; ++ks) {
            unsigned a[4][4];
#pragma unroll
            for (int mt = 0; mt < 4; ++mt)
                ldsm4(a[mt], bA + aoff + mt * 16 * 144 + ks * 32);
#pragma unroll
            for (int p = 0; p < 2; ++p) {
                unsigned bb[4];
                ldsm4(bb, bB + boff + p * 16 * 144 + ks * 32);
#pragma unroll
                for (int mt = 0; mt < 4; ++mt) {
                    mma_f16(acc[mt][2 * p], a[mt][0], a[mt][1], a[mt][2], a[mt][3],
                            bb[0], bb[2]);
                    mma_f16(acc[mt][2 * p + 1], a[mt][0], a[mt][1], a[mt][2], a[mt][3],
                            bb[1], bb[3]);
                }
            }
        }
        if (k0 < 15) {
            __half* Ad = As + ((k0 + 1) & 1) * 128 * 72;
            __half* Bd = Bs + ((k0 + 1) & 1) * 128 * 72;
#pragma unroll
            for (int i = 0; i < 4; ++i) {
                int row = r0 + i * 32;
                *(uint4*)&Ad[row * 72 + seg * 8] = ar[i];
                *(uint4*)&Bd[row * 72 + seg * 8] = br[i];
            }
        }
        __syncthreads();
    }

#pragma unroll
    for (int mt = 0; mt < 4; ++mt) {
#pragma unroll
        for (int nt = 0; nt < 4; ++nt) {
            int ncol = n0 + wn + nt * 8 + 2 * t4;
            float bx = __ldg(&bias[ncol]);
            float by = __ldg(&bias[ncol + 1]);
#pragma unroll
            for (int rr = 0; rr < 2; ++rr) {
                int m = m0 + wm + mt * 16 + g + rr * 8;
                float vx = acc[mt][nt][rr * 2] + bx;
                float vy = acc[mt][nt][rr * 2 + 1] + by;
                if (MODE == 0) {
                    int bb2 = m >> 11, ss = m & 2047;
                    int h = ncol / 192;
                    int rem = ncol - h * 192;
                    int part = rem >> 6;
                    int d = rem & 63;
                    if (part == 0) { vx *= SCALE2; vy *= SCALE2; }  // fold logit scale into Q
                    size_t dst = (((size_t)(bb2 * H_ + h)) * S_ + ss) * HD_ + d;
                    __half* dstp = (part == 0 ? g_Qh : (part == 1 ? g_Kh : g_Vh));
                    __half2 hv = __floats2half2_rn(vx, vy);
                    *(__half2*)&dstp[dst] = hv;
                } else {
                    *(float2*)&out[(size_t)m * D_ + ncol] = make_float2(vx, vy);
                }
            }
        }
    }
}

// ---------------------------------------------------------------------------
// Flash attention, fp16 mma. Softmax: max over unmasked logits (shift-
// invariance makes the overestimate harmless), f32 centering, mask applied
// as fp16 additive bias (0/-32768) from g_Bh, ex2.approx.f16x2 produces the
// packed PV A-fragments directly, row-sums via ones-matrix mma.
// ---------------------------------------------------------------------------
__global__ __launch_bounds__(256, 2) void attn_tc() {
    extern __shared__ __half shh[];
    __half* Qs = shh;                   // [128][72]
    __half* Ks = shh + 128 * 72;        // [2][64][72]
    __half* Vs = Ks + 2 * 64 * 72;      // [2][64][72]

    const int bh = blockIdx.y;
    const int q0 = blockIdx.x * 128;
    const int t = threadIdx.x;
    const int w = t >> 5;
    const int lane = t & 31;
    const int g = lane >> 2;
    const int t4 = lane & 3;

    const size_t base = (size_t)bh * (S_ * HD_);
    const __half* Qg = g_Qh + base;
    const __half* Kg = g_Kh + base;
    const __half* Vg = g_Vh + base;

    const int seg = t & 7;
    const int r0 = t >> 3;

    const unsigned sQ = smem_u32(Qs);
    const unsigned sK = smem_u32(Ks);
    const unsigned sV = smem_u32(Vs);
    const unsigned KBUF = 64 * 72 * 2;
    const unsigned qoff = (w * 16 + (lane & 15)) * 144 + (lane >> 4) * 16;
    const unsigned koff = (lane & 15) * 144 + (lane >> 4) * 16;
    const unsigned voff = (lane & 15) * 144 + (lane >> 4) * 16;

#pragma unroll
    for (int i = 0; i < 4; ++i) {
        int row = r0 + i * 32;
        *(uint4*)&Qs[row * 72 + seg * 8] =
            *(const uint4*)(Qg + (size_t)(q0 + row) * HD_ + seg * 8);
    }
    uint4 kr[2], vr[2];
#pragma unroll
    for (int i = 0; i < 2; ++i) {
        int row = r0 + i * 32;
        kr[i] = *(const uint4*)(Kg + (size_t)row * HD_ + seg * 8);
        vr[i] = *(const uint4*)(Vg + (size_t)row * HD_ + seg * 8);
    }
#pragma unroll
    for (int i = 0; i < 2; ++i) {
        int row = r0 + i * 32;
        *(uint4*)&Ks[row * 72 + seg * 8] = kr[i];
        *(uint4*)&Vs[row * 72 + seg * 8] = vr[i];
    }

    const int qrow0 = q0 + w * 16 + g;
    const int qrow1 = qrow0 + 8;
    const __half* bp0 = g_Bh + (size_t)qrow0 * S_ + 2 * t4;
    const __half* bp1 = g_Bh + (size_t)qrow1 * S_ + 2 * t4;

    float o[8][4];
#pragma unroll
    for (int nt = 0; nt < 8; ++nt)
#pragma unroll
        for (int i = 0; i < 4; ++i) o[nt][i] = 0.0f;
    float m0s = -INFINITY, m1s = -INFINITY, l0 = 0.0f, l1 = 0.0f;

    __syncthreads();

    for (int j = 0; j < 32; ++j) {
        const unsigned bK = sK + (j & 1) * KBUF;
        const unsigned bV = sV + (j & 1) * KBUF;
        if (j < 31) {
            const __half* Kn = Kg + (size_t)(j + 1) * 64 * HD_;
            const __half* Vn = Vg + (size_t)(j + 1) * 64 * HD_;
#pragma unroll
            for (int i = 0; i < 2; ++i) {
                int row = r0 + i * 32;
                kr[i] = *(const uint4*)(Kn + (size_t)row * HD_ + seg * 8);
                vr[i] = *(const uint4*)(Vn + (size_t)row * HD_ + seg * 8);
            }
        }
        // mask bias tile (half2 per nt per row)
        unsigned bw0[8], bw1[8];
#pragma unroll
        for (int nt = 0; nt < 8; ++nt) {
            bw0[nt] = __ldg((const unsigned*)(bp0 + j * 64 + nt * 8));
            bw1[nt] = __ldg((const unsigned*)(bp1 + j * 64 + nt * 8));
        }

        // S = Q @ K^T (logits pre-scaled via Q)
        float sc[8][4];
#pragma unroll
        for (int nt = 0; nt < 8; ++nt)
#pragma unroll
            for (int i = 0; i < 4; ++i) sc[nt][i] = 0.0f;
#pragma unroll
        for (int ks = 0; ks < 4; ++ks) {
            unsigned qa[4];
            ldsm4(qa, sQ + qoff + ks * 32);
#pragma unroll
            for (int p = 0; p < 4; ++p) {
                unsigned kb[4];
                ldsm4(kb, bK + koff + p * 16 * 144 + ks * 32);
                mma_f16(sc[2 * p], qa[0], qa[1], qa[2], qa[3], kb[0], kb[2]);
                mma_f16(sc[2 * p + 1], qa[0], qa[1], qa[2], qa[3], kb[1], kb[3]);
            }
        }

        // running max over (unmasked) logits — overestimate is harmless
        float mx0 = -INFINITY, mx1 = -INFINITY;
#pragma unroll
        for (int nt = 0; nt < 8; ++nt) {
            mx0 = fmaxf(mx0, fmaxf(sc[nt][0], sc[nt][1]));
            mx1 = fmaxf(mx1, fmaxf(sc[nt][2], sc[nt][3]));
        }
        mx0 = fmaxf(mx0, __shfl_xor_sync(0xffffffffu, mx0, 1));
        mx0 = fmaxf(mx0, __shfl_xor_sync(0xffffffffu, mx0, 2));
        mx1 = fmaxf(mx1, __shfl_xor_sync(0xffffffffu, mx1, 1));
        mx1 = fmaxf(mx1, __shfl_xor_sync(0xffffffffu, mx1, 2));
        float mn0 = fmaxf(m0s, mx0), mn1 = fmaxf(m1s, mx1);
        float al0 = ex2(m0s - mn0), al1 = ex2(m1s - mn1);
        m0s = mn0; m1s = mn1;
#pragma unroll
        for (int nt = 0; nt < 8; ++nt) {
            o[nt][0] *= al0; o[nt][1] *= al0;
            o[nt][2] *= al1; o[nt][3] *= al1;
        }

        // center (f32) -> pack -> +mask bias (half) -> exp (half2)
        unsigned ph_lo[8], ph_hi[8];
#pragma unroll
        for (int nt = 0; nt < 8; ++nt) {
            ph_lo[nt] = ex2h2(hadd2u(h2(sc[nt][0] - mn0, sc[nt][1] - mn0), bw0[nt]));
            ph_hi[nt] = ex2h2(hadd2u(h2(sc[nt][2] - mn1, sc[nt][3] - mn1), bw1[nt]));
        }

        // row sums via ones-matrix mma (exact sums of the same half p's)
        float rs[4] = {0.0f, 0.0f, 0.0f, 0.0f};
#pragma unroll
        for (int kt = 0; kt < 4; ++kt)
            mma_f16(rs, ph_lo[2 * kt], ph_hi[2 * kt], ph_lo[2 * kt + 1],
                    ph_hi[2 * kt + 1], ONESH2, ONESH2);
        l0 = al0 * l0 + rs[0];
        l1 = al1 * l1 + rs[2];

        // O += P @ V
#pragma unroll
        for (int kt = 0; kt < 4; ++kt) {
            unsigned a0 = ph_lo[2 * kt];
            unsigned a1 = ph_hi[2 * kt];
            unsigned a2 = ph_lo[2 * kt + 1];
            unsigned a3 = ph_hi[2 * kt + 1];
#pragma unroll
            for (int q = 0; q < 4; ++q) {
                unsigned vb[4];
                ldsm4t(vb, bV + voff + kt * 16 * 144 + q * 32);
                mma_f16(o[2 * q], a0, a1, a2, a3, vb[0], vb[1]);
                mma_f16(o[2 * q + 1], a0, a1, a2, a3, vb[2], vb[3]);
            }
        }

        if (j < 31) {
            __half* Kd = Ks + ((j + 1) & 1) * 64 * 72;
            __half* Vd = Vs + ((j + 1) & 1) * 64 * 72;
#pragma unroll
            for (int i = 0; i < 2; ++i) {
                int row = r0 + i * 32;
                *(uint4*)&Kd[row * 72 + seg * 8] = kr[i];
                *(uint4*)&Vd[row * 72 + seg * 8] = vr[i];
            }
        }
        __syncthreads();
    }

    // epilogue
    const int bb = bh >> 4;
    const int h = bh & 15;
    float inv0 = 1.0f / l0, inv1 = 1.0f / l1;
#pragma unroll
    for (int nt = 0; nt < 8; ++nt) {
        int dcol = h * 64 + nt * 8 + 2 * t4;
        size_t rr0 = ((size_t)bb * S_ + qrow0) * D_ + dcol;
        size_t rr1 = ((size_t)bb * S_ + qrow1) * D_ + dcol;
        __half2 v0 = __floats2half2_rn(o[nt][0] * inv0, o[nt][1] * inv0);
        __half2 v1 = __floats2half2_rn(o[nt][2] * inv1, o[nt][3] * inv1);
        *(__half2*)&g_Ch[rr0] = v0;
        *(__half2*)&g_Ch[rr1] = v1;
    }
}

// ---------------------------------------------------------------------------
extern "C" void kernel_launch(void* const* d_in, const int* in_sizes, int n_in,
                              void* d_out, int out_size) {
    const float* x     = (const float*)d_in[0];
    const int*   mask  = (const int*)d_in[1];
    const float* w_qkv = (const float*)d_in[2];
    const float* b_qkv = (const float*)d_in[3];
    const float* w_o   = (const float*)d_in[4];
    const float* b_o   = (const float*)d_in[5];
    float* out = (float*)d_out;

    const int gemm_smem = 4 * 128 * 72 * 2;              // 73728
    const int attn_smem = (128 * 72 + 4 * 64 * 72) * 2;  // 55296

    cudaFuncSetAttribute(gemm_tc<0>, cudaFuncAttributeMaxDynamicSharedMemorySize, gemm_smem);
    cudaFuncSetAttribute(gemm_tc<1>, cudaFuncAttributeMaxDynamicSharedMemorySize, gemm_smem);
    cudaFuncSetAttribute(attn_tc, cudaFuncAttributeMaxDynamicSharedMemorySize, attn_smem);

    // 0) one-time prep
    biasprep<<<S_ * S_ / 2048, 256>>>(mask);
    __half *dXh, *dW1h, *dW2h, *dCh;
    cudaGetSymbolAddress((void**)&dXh, g_Xh);
    cudaGetSymbolAddress((void**)&dW1h, g_W1h);
    cudaGetSymbolAddress((void**)&dW2h, g_W2h);
    cudaGetSymbolAddress((void**)&dCh, g_Ch);
    conv_h<<<B_ * S_ * D_ / 2048, 256>>>(x, dXh);
    conv_h<<<3 * D_ * D_ / 2048, 256>>>(w_qkv, dW1h);
    conv_h<<<D_ * D_ / 2048, 256>>>(w_o, dW2h);

    // 1) QKV projection
    gemm_tc<0><<<dim3(3072 / 128, 4096 / 128), 256, gemm_smem>>>(dXh, dW1h, b_qkv, nullptr);

    // 2) flash attention
    attn_tc<<<dim3(S_ / 128, B_ * H_), 256, attn_smem>>>();

    // 3) output projection
    gemm_tc<1><<<dim3(1024 / 128, 4096 / 128), 256, gemm_smem>>>(dCh, dW2h, b_o, out);
}

// round 11
// speedup vs baseline: 29.5792x; 1.0126x over previous
#include <cuda_runtime.h>
#include <cuda_fp16.h>
#include <math.h>
#include <cstdint>

#define B_ 2
#define S_ 2048
#define D_ 1024
#define H_ 16
#define HD_ 64
#define SCALE2 0.1803368801111204f
#define ONESH2 0x3C003C00u

// Scratch (device globals: allocation-free rule)
__device__ __half g_Qh[B_ * H_ * S_ * HD_];
__device__ __half g_Kh[B_ * H_ * S_ * HD_];
__device__ __half g_Vh[B_ * H_ * S_ * HD_];
__device__ __half g_Ch[B_ * S_ * D_];
__device__ __half g_Xh[B_ * S_ * D_];
__device__ __half g_W1h[3 * D_ * D_];
__device__ __half g_W2h[D_ * D_];
__device__ __half g_Bh[S_ * S_];   // additive mask bias: 0 or -32768

__device__ __forceinline__ float ex2(float x) {
    float y;
    asm("ex2.approx.f32 %0, %1;" : "=f"(y) : "f"(x));
    return y;
}
__device__ __forceinline__ unsigned ex2h2(unsigned x) {
    unsigned y;
    asm("ex2.approx.f16x2 %0, %1;" : "=r"(y) : "r"(x));
    return y;
}
__device__ __forceinline__ unsigned h2(float a, float b) {
    __half2 h = __floats2half2_rn(a, b);
    return *(unsigned*)&h;
}
__device__ __forceinline__ unsigned hadd2u(unsigned a, unsigned b) {
    __half2 r = __hadd2(*(__half2*)&a, *(__half2*)&b);
    return *(unsigned*)&r;
}
__device__ __forceinline__ void mma_f16(float c[4], unsigned a0, unsigned a1,
                                        unsigned a2, unsigned a3,
                                        unsigned b0, unsigned b1) {
    asm volatile(
        "mma.sync.aligned.m16n8k16.row.col.f32.f16.f16.f32 "
        "{%0,%1,%2,%3}, {%4,%5,%6,%7}, {%8,%9}, {%0,%1,%2,%3};"
        : "+f"(c[0]), "+f"(c[1]), "+f"(c[2]), "+f"(c[3])
        : "r"(a0), "r"(a1), "r"(a2), "r"(a3), "r"(b0), "r"(b1));
}
__device__ __forceinline__ unsigned smem_u32(const void* p) {
    return (unsigned)__cvta_generic_to_shared(p);
}
__device__ __forceinline__ void ldsm4(unsigned r[4], unsigned addr) {
    asm volatile(
        "ldmatrix.sync.aligned.m8n8.x4.shared.b16 {%0,%1,%2,%3}, [%4];"
        : "=r"(r[0]), "=r"(r[1]), "=r"(r[2]), "=r"(r[3]) : "r"(addr));
}
__device__ __forceinline__ void ldsm4t(unsigned r[4], unsigned addr) {
    asm volatile(
        "ldmatrix.sync.aligned.m8n8.x4.trans.shared.b16 {%0,%1,%2,%3}, [%4];"
        : "=r"(r[0]), "=r"(r[1]), "=r"(r[2]), "=r"(r[3]) : "r"(addr));
}

// ---------------------------------------------------------------------------
// Expand int mask -> additive fp16 bias (0 or -32768). 8 elems/thread.
__global__ __launch_bounds__(256) void biasprep(const int* __restrict__ mask) {
    int i = (blockIdx.x * 256 + threadIdx.x) * 8;
    int4 m0 = __ldg((const int4*)(mask + i));
    int4 m1 = __ldg((const int4*)(mask + i + 4));
    uint4 u;
    u.x = (m0.x ? 0u : 0xF800u) | (m0.y ? 0u : 0xF8000000u);
    u.y = (m0.z ? 0u : 0xF800u) | (m0.w ? 0u : 0xF8000000u);
    u.z = (m1.x ? 0u : 0xF800u) | (m1.y ? 0u : 0xF8000000u);
    u.w = (m1.z ? 0u : 0xF800u) | (m1.w ? 0u : 0xF8000000u);
    *(uint4*)((__half*)g_Bh + i) = u;
}

// f32 -> f16 bulk convert (one-time, 8 elems/thread)
__global__ __launch_bounds__(256) void conv_h(const float* __restrict__ in,
                                              __half* __restrict__ outp) {
    int i = (blockIdx.x * 256 + threadIdx.x) * 8;
    float4 v0 = *(const float4*)(in + i);
    float4 v1 = *(const float4*)(in + i + 4);
    uint4 u;
    u.x = h2(v0.x, v0.y); u.y = h2(v0.z, v0.w);
    u.z = h2(v1.x, v1.y); u.w = h2(v1.z, v1.w);
    *(uint4*)(outp + i) = u;
}

// ---------------------------------------------------------------------------
// fp16 tensor-core GEMM (unchanged from round 10).
// ---------------------------------------------------------------------------
template <int MODE>
__global__ __launch_bounds__(256, 2) void gemm_tc(const __half* __restrict__ A,
                                                  const __half* __restrict__ W,
                                                  const float* __restrict__ bias,
                                                  float* __restrict__ out) {
    extern __shared__ __half shh[];
    __half* As = shh;                  // [2][128][72]
    __half* Bs = shh + 2 * 128 * 72;   // [2][128][72]

    const int m0 = blockIdx.y * 128;
    const int n0 = blockIdx.x * 128;
    const int t = threadIdx.x;
    const int w = t >> 5;
    const int lane = t & 31;
    const int g = lane >> 2;
    const int t4 = lane & 3;
    const int wm = (w >> 2) * 64;
    const int wn = (w & 3) * 32;

    const int seg = t & 7;
    const int r0 = t >> 3;

    const unsigned sA = smem_u32(As);
    const unsigned sB = smem_u32(Bs);
    const unsigned BUF = 128 * 72 * 2;
    const unsigned aoff = (wm + (lane & 15)) * 144 + (lane >> 4) * 16;
    const unsigned boff = (wn + (lane & 15)) * 144 + (lane >> 4) * 16;

    uint4 ar[4], br[4];
#pragma unroll
    for (int i = 0; i < 4; ++i) {
        int row = r0 + i * 32;
        ar[i] = *(const uint4*)(A + (size_t)(m0 + row) * D_ + seg * 8);
        br[i] = *(const uint4*)(W + (size_t)(n0 + row) * D_ + seg * 8);
    }
#pragma unroll
    for (int i = 0; i < 4; ++i) {
        int row = r0 + i * 32;
        *(uint4*)&As[row * 72 + seg * 8] = ar[i];
        *(uint4*)&Bs[row * 72 + seg * 8] = br[i];
    }
    __syncthreads();

    float acc[4][4][4];
#pragma unroll
    for (int mt = 0; mt < 4; ++mt)
#pragma unroll
        for (int nt = 0; nt < 4; ++nt)
#pragma unroll
            for (int i = 0; i < 4; ++i) acc[mt][nt][i] = 0.0f;

    for (int k0 = 0; k0 < 16; ++k0) {
        const unsigned bA = sA + (k0 & 1) * BUF;
        const unsigned bB = sB + (k0 & 1) * BUF;
        if (k0 < 15) {
            int ko = (k0 + 1) * 64;
#pragma unroll
            for (int i = 0; i < 4; ++i) {
                int row = r0 + i * 32;
                ar[i] = *(const uint4*)(A + (size_t)(m0 + row) * D_ + ko + seg * 8);
                br[i] = *(const uint4*)(W + (size_t)(n0 + row) * D_ + ko + seg * 8);
            }
        }
#pragma unroll
        for (int ks = 0; ks < 4; ++ks) {
            unsigned a[4][4];
#pragma unroll
            for (int mt = 0; mt < 4; ++mt)
                ldsm4(a[mt], bA + aoff + mt * 16 * 144 + ks * 32);
#pragma unroll
            for (int p = 0; p < 2; ++p) {
                unsigned bb[4];
                ldsm4(bb, bB + boff + p * 16 * 144 + ks * 32);
#pragma unroll
                for (int mt = 0; mt < 4; ++mt) {
                    mma_f16(acc[mt][2 * p], a[mt][0], a[mt][1], a[mt][2], a[mt][3],
                            bb[0], bb[2]);
                    mma_f16(acc[mt][2 * p + 1], a[mt][0], a[mt][1], a[mt][2], a[mt][3],
                            bb[1], bb[3]);
                }
            }
        }
        if (k0 < 15) {
            __half* Ad = As + ((k0 + 1) & 1) * 128 * 72;
            __half* Bd = Bs + ((k0 + 1) & 1) * 128 * 72;
#pragma unroll
            for (int i = 0; i < 4; ++i) {
                int row = r0 + i * 32;
                *(uint4*)&Ad[row * 72 + seg * 8] = ar[i];
                *(uint4*)&Bd[row * 72 + seg * 8] = br[i];
            }
        }
        __syncthreads();
    }

#pragma unroll
    for (int mt = 0; mt < 4; ++mt) {
#pragma unroll
        for (int nt = 0; nt < 4; ++nt) {
            int ncol = n0 + wn + nt * 8 + 2 * t4;
            float bx = __ldg(&bias[ncol]);
            float by = __ldg(&bias[ncol + 1]);
#pragma unroll
            for (int rr = 0; rr < 2; ++rr) {
                int m = m0 + wm + mt * 16 + g + rr * 8;
                float vx = acc[mt][nt][rr * 2] + bx;
                float vy = acc[mt][nt][rr * 2 + 1] + by;
                if (MODE == 0) {
                    int bb2 = m >> 11, ss = m & 2047;
                    int h = ncol / 192;
                    int rem = ncol - h * 192;
                    int part = rem >> 6;
                    int d = rem & 63;
                    if (part == 0) { vx *= SCALE2; vy *= SCALE2; }
                    size_t dst = (((size_t)(bb2 * H_ + h)) * S_ + ss) * HD_ + d;
                    __half* dstp = (part == 0 ? g_Qh : (part == 1 ? g_Kh : g_Vh));
                    __half2 hv = __floats2half2_rn(vx, vy);
                    *(__half2*)&dstp[dst] = hv;
                } else {
                    *(float2*)&out[(size_t)m * D_ + ncol] = make_float2(vx, vy);
                }
            }
        }
    }
}

// ---------------------------------------------------------------------------
// Flash attention, fp16 mma. 4-stage K/V ring buffer, staged 2 tiles ahead,
// ONE barrier per 2 j-tiles (warps may drift a full tile -> softmax of one
// warp overlaps mma issue of another). Softmax: unmasked running max, f32
// centering, fp16 additive mask bias, ex2.f16x2 -> packed PV A-frags,
// row sums via ones-matrix mma.
// ---------------------------------------------------------------------------
__global__ __launch_bounds__(256, 2) void attn_tc() {
    extern __shared__ __half shh[];
    __half* Qs = shh;                   // [128][72]
    __half* Ks = shh + 128 * 72;        // [4][64][72]
    __half* Vs = Ks + 4 * 64 * 72;      // [4][64][72]

    const int bh = blockIdx.y;
    const int q0 = blockIdx.x * 128;
    const int t = threadIdx.x;
    const int w = t >> 5;
    const int lane = t & 31;
    const int g = lane >> 2;
    const int t4 = lane & 3;

    const size_t base = (size_t)bh * (S_ * HD_);
    const __half* Qg = g_Qh + base;
    const __half* Kg = g_Kh + base;
    const __half* Vg = g_Vh + base;

    const int seg = t & 7;
    const int r0 = t >> 3;

    const unsigned sQ = smem_u32(Qs);
    const unsigned sK = smem_u32(Ks);
    const unsigned sV = smem_u32(Vs);
    const unsigned KBUF = 64 * 72 * 2;   // bytes per ring stage
    const unsigned qoff = (w * 16 + (lane & 15)) * 144 + (lane >> 4) * 16;
    const unsigned koff = (lane & 15) * 144 + (lane >> 4) * 16;
    const unsigned voff = (lane & 15) * 144 + (lane >> 4) * 16;

    // stage Q
#pragma unroll
    for (int i = 0; i < 4; ++i) {
        int row = r0 + i * 32;
        *(uint4*)&Qs[row * 72 + seg * 8] =
            *(const uint4*)(Qg + (size_t)(q0 + row) * HD_ + seg * 8);
    }
    // stage K/V tiles 0,1 into ring stages 0,1
#pragma unroll
    for (int tile = 0; tile < 2; ++tile) {
#pragma unroll
        for (int i = 0; i < 2; ++i) {
            int row = r0 + i * 32;
            *(uint4*)&Ks[tile * 64 * 72 + row * 72 + seg * 8] =
                *(const uint4*)(Kg + ((size_t)tile * 64 + row) * HD_ + seg * 8);
            *(uint4*)&Vs[tile * 64 * 72 + row * 72 + seg * 8] =
                *(const uint4*)(Vg + ((size_t)tile * 64 + row) * HD_ + seg * 8);
        }
    }

    const int qrow0 = q0 + w * 16 + g;
    const int qrow1 = qrow0 + 8;
    const __half* bp0 = g_Bh + (size_t)qrow0 * S_ + 2 * t4;
    const __half* bp1 = g_Bh + (size_t)qrow1 * S_ + 2 * t4;

    float o[8][4];
#pragma unroll
    for (int nt = 0; nt < 8; ++nt)
#pragma unroll
        for (int i = 0; i < 4; ++i) o[nt][i] = 0.0f;
    float m0s = -INFINITY, m1s = -INFINITY, l0 = 0.0f, l1 = 0.0f;

    for (int jj = 0; jj < 32; jj += 2) {
        // barrier: ring stages jj%4,(jj+1)%4 fully staged; stages (jj+2)%4,
        // (jj+3)%4 fully consumed (as tiles jj-2, jj-1) by all warps.
        __syncthreads();
        const unsigned ph = (unsigned)(jj & 2);  // 0 or 2
#pragma unroll
        for (int u = 0; u < 2; ++u) {
            const int j = jj + u;
            const unsigned bK = sK + (ph + u) * KBUF;
            const unsigned bV = sV + (ph + u) * KBUF;
            const bool pf = (j + 2 < 32);
            uint4 kr[2], vr[2];
            if (pf) {
                const __half* Kn = Kg + (size_t)(j + 2) * 64 * HD_;
                const __half* Vn = Vg + (size_t)(j + 2) * 64 * HD_;
#pragma unroll
                for (int i = 0; i < 2; ++i) {
                    int row = r0 + i * 32;
                    kr[i] = *(const uint4*)(Kn + (size_t)row * HD_ + seg * 8);
                    vr[i] = *(const uint4*)(Vn + (size_t)row * HD_ + seg * 8);
                }
            }
            // mask bias tile
            unsigned bw0[8], bw1[8];
#pragma unroll
            for (int nt = 0; nt < 8; ++nt) {
                bw0[nt] = __ldg((const unsigned*)(bp0 + j * 64 + nt * 8));
                bw1[nt] = __ldg((const unsigned*)(bp1 + j * 64 + nt * 8));
            }

            // S = Q @ K^T (logits pre-scaled via Q)
            float sc[8][4];
#pragma unroll
            for (int nt = 0; nt < 8; ++nt)
#pragma unroll
                for (int i = 0; i < 4; ++i) sc[nt][i] = 0.0f;
#pragma unroll
            for (int ks = 0; ks < 4; ++ks) {
                unsigned qa[4];
                ldsm4(qa, sQ + qoff + ks * 32);
#pragma unroll
                for (int p = 0; p < 4; ++p) {
                    unsigned kb[4];
                    ldsm4(kb, bK + koff + p * 16 * 144 + ks * 32);
                    mma_f16(sc[2 * p], qa[0], qa[1], qa[2], qa[3], kb[0], kb[2]);
                    mma_f16(sc[2 * p + 1], qa[0], qa[1], qa[2], qa[3], kb[1], kb[3]);
                }
            }

            // running max over unmasked logits (overestimate harmless)
            float mx0 = -INFINITY, mx1 = -INFINITY;
#pragma unroll
            for (int nt = 0; nt < 8; ++nt) {
                mx0 = fmaxf(mx0, fmaxf(sc[nt][0], sc[nt][1]));
                mx1 = fmaxf(mx1, fmaxf(sc[nt][2], sc[nt][3]));
            }
            mx0 = fmaxf(mx0, __shfl_xor_sync(0xffffffffu, mx0, 1));
            mx0 = fmaxf(mx0, __shfl_xor_sync(0xffffffffu, mx0, 2));
            mx1 = fmaxf(mx1, __shfl_xor_sync(0xffffffffu, mx1, 1));
            mx1 = fmaxf(mx1, __shfl_xor_sync(0xffffffffu, mx1, 2));
            float mn0 = fmaxf(m0s, mx0), mn1 = fmaxf(m1s, mx1);
            float al0 = ex2(m0s - mn0), al1 = ex2(m1s - mn1);
            m0s = mn0; m1s = mn1;
#pragma unroll
            for (int nt = 0; nt < 8; ++nt) {
                o[nt][0] *= al0; o[nt][1] *= al0;
                o[nt][2] *= al1; o[nt][3] *= al1;
            }

            // center (f32) -> pack -> +mask bias (half) -> exp (half2)
            unsigned ph_lo[8], ph_hi[8];
#pragma unroll
            for (int nt = 0; nt < 8; ++nt) {
                ph_lo[nt] = ex2h2(hadd2u(h2(sc[nt][0] - mn0, sc[nt][1] - mn0), bw0[nt]));
                ph_hi[nt] = ex2h2(hadd2u(h2(sc[nt][2] - mn1, sc[nt][3] - mn1), bw1[nt]));
            }

            // row sums via ones-matrix mma
            float rs[4] = {0.0f, 0.0f, 0.0f, 0.0f};
#pragma unroll
            for (int kt = 0; kt < 4; ++kt)
                mma_f16(rs, ph_lo[2 * kt], ph_hi[2 * kt], ph_lo[2 * kt + 1],
                        ph_hi[2 * kt + 1], ONESH2, ONESH2);
            l0 = al0 * l0 + rs[0];
            l1 = al1 * l1 + rs[2];

            // O += P @ V
#pragma unroll
            for (int kt = 0; kt < 4; ++kt) {
                unsigned a0 = ph_lo[2 * kt];
                unsigned a1 = ph_hi[2 * kt];
                unsigned a2 = ph_lo[2 * kt + 1];
                unsigned a3 = ph_hi[2 * kt + 1];
#pragma unroll
                for (int q = 0; q < 4; ++q) {
                    unsigned vb[4];
                    ldsm4t(vb, bV + voff + kt * 16 * 144 + q * 32);
                    mma_f16(o[2 * q], a0, a1, a2, a3, vb[0], vb[1]);
                    mma_f16(o[2 * q + 1], a0, a1, a2, a3, vb[2], vb[3]);
                }
            }

            // stage tile j+2 into ring stage (j+2)%4 — disjoint from all
            // stages read in this barrier window.
            if (pf) {
                __half* Kd = Ks + ((ph + u + 2) & 3) * 64 * 72;
                __half* Vd = Vs + ((ph + u + 2) & 3) * 64 * 72;
#pragma unroll
                for (int i = 0; i < 2; ++i) {
                    int row = r0 + i * 32;
                    *(uint4*)&Kd[row * 72 + seg * 8] = kr[i];
                    *(uint4*)&Vd[row * 72 + seg * 8] = vr[i];
                }
            }
        }
    }

    // epilogue
    const int bb = bh >> 4;
    const int h = bh & 15;
    float inv0 = 1.0f / l0, inv1 = 1.0f / l1;
#pragma unroll
    for (int nt = 0; nt < 8; ++nt) {
        int dcol = h * 64 + nt * 8 + 2 * t4;
        size_t rr0 = ((size_t)bb * S_ + qrow0) * D_ + dcol;
        size_t rr1 = ((size_t)bb * S_ + qrow1) * D_ + dcol;
        __half2 v0 = __floats2half2_rn(o[nt][0] * inv0, o[nt][1] * inv0);
        __half2 v1 = __floats2half2_rn(o[nt][2] * inv1, o[nt][3] * inv1);
        *(__half2*)&g_Ch[rr0] = v0;
        *(__half2*)&g_Ch[rr1] = v1;
    }
}

// ---------------------------------------------------------------------------
extern "C" void kernel_launch(void* const* d_in, const int* in_sizes, int n_in,
                              void* d_out, int out_size) {
    const float* x     = (const float*)d_in[0];
    const int*   mask  = (const int*)d_in[1];
    const float* w_qkv = (const float*)d_in[2];
    const float* b_qkv = (const float*)d_in[3];
    const float* w_o   = (const float*)d_in[4];
    const float* b_o   = (const float*)d_in[5];
    float* out = (float*)d_out;

    const int gemm_smem = 4 * 128 * 72 * 2;              // 73728
    const int attn_smem = (128 * 72 + 8 * 64 * 72) * 2;  // 92160

    cudaFuncSetAttribute(gemm_tc<0>, cudaFuncAttributeMaxDynamicSharedMemorySize, gemm_smem);
    cudaFuncSetAttribute(gemm_tc<1>, cudaFuncAttributeMaxDynamicSharedMemorySize, gemm_smem);
    cudaFuncSetAttribute(attn_tc, cudaFuncAttributeMaxDynamicSharedMemorySize, attn_smem);

    // 0) one-time prep
    biasprep<<<S_ * S_ / 2048, 256>>>(mask);
    __half *dXh, *dW1h, *dW2h, *dCh;
    cudaGetSymbolAddress((void**)&dXh, g_Xh);
    cudaGetSymbolAddress((void**)&dW1h, g_W1h);
    cudaGetSymbolAddress((void**)&dW2h, g_W2h);
    cudaGetSymbolAddress((void**)&dCh, g_Ch);
    conv_h<<<B_ * S_ * D_ / 2048, 256>>>(x, dXh);
    conv_h<<<3 * D_ * D_ / 2048, 256>>>(w_qkv, dW1h);
    conv_h<<<D_ * D_ / 2048, 256>>>(w_o, dW2h);

    // 1) QKV projection
    gemm_tc<0><<<dim3(3072 / 128, 4096 / 128), 256, gemm_smem>>>(dXh, dW1h, b_qkv, nullptr);

    // 2) flash attention
    attn_tc<<<dim3(S_ / 128, B_ * H_), 256, attn_smem>>>();

    // 3) output projection
    gemm_tc<1><<<dim3(1024 / 128, 4096 / 128), 256, gemm_smem>>>(dCh, dW2h, b_o, out);
}

// round 13
// speedup vs baseline: 35.3183x; 1.1940x over previous
#include <cuda_runtime.h>
#include <cuda_fp16.h>
#include <math.h>
#include <cstdint>

#define B_ 2
#define S_ 2048
#define D_ 1024
#define H_ 16
#define HD_ 64
#define SCALE2 0.1803368801111204f
#define ONESH2 0x3C003C00u

// Scratch (device globals: allocation-free rule)
__device__ __half g_Qh[B_ * H_ * S_ * HD_];
__device__ __half g_Kh[B_ * H_ * S_ * HD_];
__device__ __half g_Vh[B_ * H_ * S_ * HD_];
__device__ __half g_Ch[B_ * S_ * D_];
__device__ __half g_Xh[B_ * S_ * D_];
__device__ __half g_W1h[3 * D_ * D_];
__device__ __half g_W2h[D_ * D_];
// mask bias, fragment-major: word(r, j, t4, nt) at r*1024 + j*32 + t4*8 + nt
__device__ __half g_Bh[S_ * S_];

__device__ __forceinline__ float ex2(float x) {
    float y;
    asm("ex2.approx.f32 %0, %1;" : "=f"(y) : "f"(x));
    return y;
}
__device__ __forceinline__ unsigned ex2h2(unsigned x) {
    unsigned y;
    asm("ex2.approx.f16x2 %0, %1;" : "=r"(y) : "r"(x));
    return y;
}
__device__ __forceinline__ unsigned h2(float a, float b) {
    __half2 h = __floats2half2_rn(a, b);
    return *(unsigned*)&h;
}
__device__ __forceinline__ unsigned hadd2u(unsigned a, unsigned b) {
    __half2 r = __hadd2(*(__half2*)&a, *(__half2*)&b);
    return *(unsigned*)&r;
}
__device__ __forceinline__ void mma_f16(float c[4], unsigned a0, unsigned a1,
                                        unsigned a2, unsigned a3,
                                        unsigned b0, unsigned b1) {
    asm volatile(
        "mma.sync.aligned.m16n8k16.row.col.f32.f16.f16.f32 "
        "{%0,%1,%2,%3}, {%4,%5,%6,%7}, {%8,%9}, {%0,%1,%2,%3};"
        : "+f"(c[0]), "+f"(c[1]), "+f"(c[2]), "+f"(c[3])
        : "r"(a0), "r"(a1), "r"(a2), "r"(a3), "r"(b0), "r"(b1));
}
__device__ __forceinline__ unsigned smem_u32(const void* p) {
    return (unsigned)__cvta_generic_to_shared(p);
}
__device__ __forceinline__ void ldsm4(unsigned r[4], unsigned addr) {
    asm volatile(
        "ldmatrix.sync.aligned.m8n8.x4.shared.b16 {%0,%1,%2,%3}, [%4];"
        : "=r"(r[0]), "=r"(r[1]), "=r"(r[2]), "=r"(r[3]) : "r"(addr));
}
__device__ __forceinline__ void ldsm4t(unsigned r[4], unsigned addr) {
    asm volatile(
        "ldmatrix.sync.aligned.m8n8.x4.trans.shared.b16 {%0,%1,%2,%3}, [%4];"
        : "=r"(r[0]), "=r"(r[1]), "=r"(r[2]), "=r"(r[3]) : "r"(addr));
}
__device__ __forceinline__ void cp16(unsigned dst, const void* src) {
    asm volatile("cp.async.cg.shared.global [%0], [%1], 16;" ::"r"(dst), "l"(src));
}
#define CP_COMMIT() asm volatile("cp.async.commit_group;" ::: "memory")
template <int N>
__device__ __forceinline__ void cp_wait() {
    asm volatile("cp.async.wait_group %0;" ::"n"(N) : "memory");
}

// ---------------------------------------------------------------------------
// mask -> additive fp16 bias (0 / -32768), fragment-major layout.
// Total words = S*S/2 = 2,097,152; 4 words/thread, 256 thr -> 2048 blocks.
__global__ __launch_bounds__(256) void biasprep(const int* __restrict__ mask) {
    int wbase = (blockIdx.x * 256 + threadIdx.x) * 4;   // word index, 4/thread
    unsigned wds[4];
#pragma unroll
    for (int q = 0; q < 4; ++q) {
        int wd = wbase + q;
        int r = wd >> 10, rem = wd & 1023;
        int j = rem >> 5, t4 = (rem >> 3) & 3, nt = rem & 7;
        int c = j * 64 + nt * 8 + 2 * t4;
        int m0 = __ldg(mask + (size_t)r * S_ + c);
        int m1 = __ldg(mask + (size_t)r * S_ + c + 1);
        wds[q] = (m0 ? 0u : 0xF800u) | (m1 ? 0u : 0xF8000000u);
    }
    *(uint4*)((unsigned*)g_Bh + wbase) = make_uint4(wds[0], wds[1], wds[2], wds[3]);
}

// single-launch f32 -> f16 convert for x, w_qkv, w_o
__global__ __launch_bounds__(256) void conv_all(const float* __restrict__ x,
                                                const float* __restrict__ w1,
                                                const float* __restrict__ w2) {
    int b = blockIdx.x;
    const float* src;
    __half* dst;
    int base;
    if (b < 2048)      { src = x;  dst = g_Xh;  base = b; }
    else if (b < 3584) { src = w1; dst = g_W1h; base = b - 2048; }
    else               { src = w2; dst = g_W2h; base = b - 3584; }
    int i = (base * 256 + threadIdx.x) * 8;
    float4 v0 = *(const float4*)(src + i);
    float4 v1 = *(const float4*)(src + i + 4);
    uint4 u;
    u.x = h2(v0.x, v0.y); u.y = h2(v0.z, v0.w);
    u.z = h2(v1.x, v1.y); u.w = h2(v1.z, v1.w);
    *(uint4*)(dst + i) = u;
}

// ---------------------------------------------------------------------------
// fp16 tensor-core GEMM (unchanged from round 11).
// ---------------------------------------------------------------------------
template <int MODE>
__global__ __launch_bounds__(256, 2) void gemm_tc(const __half* __restrict__ A,
                                                  const __half* __restrict__ W,
                                                  const float* __restrict__ bias,
                                                  float* __restrict__ out) {
    extern __shared__ __half shh[];
    __half* As = shh;                  // [2][128][72]
    __half* Bs = shh + 2 * 128 * 72;   // [2][128][72]

    const int m0 = blockIdx.y * 128;
    const int n0 = blockIdx.x * 128;
    const int t = threadIdx.x;
    const int w = t >> 5;
    const int lane = t & 31;
    const int g = lane >> 2;
    const int t4 = lane & 3;
    const int wm = (w >> 2) * 64;
    const int wn = (w & 3) * 32;

    const int seg = t & 7;
    const int r0 = t >> 3;

    const unsigned sA = smem_u32(As);
    const unsigned sB = smem_u32(Bs);
    const unsigned BUF = 128 * 72 * 2;
    const unsigned aoff = (wm + (lane & 15)) * 144 + (lane >> 4) * 16;
    const unsigned boff = (wn + (lane & 15)) * 144 + (lane >> 4) * 16;

    uint4 ar[4], br[4];
#pragma unroll
    for (int i = 0; i < 4; ++i) {
        int row = r0 + i * 32;
        ar[i] = *(const uint4*)(A + (size_t)(m0 + row) * D_ + seg * 8);
        br[i] = *(const uint4*)(W + (size_t)(n0 + row) * D_ + seg * 8);
    }
#pragma unroll
    for (int i = 0; i < 4; ++i) {
        int row = r0 + i * 32;
        *(uint4*)&As[row * 72 + seg * 8] = ar[i];
        *(uint4*)&Bs[row * 72 + seg * 8] = br[i];
    }
    __syncthreads();

    float acc[4][4][4];
#pragma unroll
    for (int mt = 0; mt < 4; ++mt)
#pragma unroll
        for (int nt = 0; nt < 4; ++nt)
#pragma unroll
            for (int i = 0; i < 4; ++i) acc[mt][nt][i] = 0.0f;

    for (int k0 = 0; k0 < 16; ++k0) {
        const unsigned bA = sA + (k0 & 1) * BUF;
        const unsigned bB = sB + (k0 & 1) * BUF;
        if (k0 < 15) {
            int ko = (k0 + 1) * 64;
#pragma unroll
            for (int i = 0; i < 4; ++i) {
                int row = r0 + i * 32;
                ar[i] = *(const uint4*)(A + (size_t)(m0 + row) * D_ + ko + seg * 8);
                br[i] = *(const uint4*)(W + (size_t)(n0 + row) * D_ + ko + seg * 8);
            }
        }
#pragma unroll
        for (int ks = 0; ks < 4; ++ks) {
            unsigned a[4][4];
#pragma unroll
            for (int mt = 0; mt < 4; ++mt)
                ldsm4(a[mt], bA + aoff + mt * 16 * 144 + ks * 32);
#pragma unroll
            for (int p = 0; p < 2; ++p) {
                unsigned bb[4];
                ldsm4(bb, bB + boff + p * 16 * 144 + ks * 32);
#pragma unroll
                for (int mt = 0; mt < 4; ++mt) {
                    mma_f16(acc[mt][2 * p], a[mt][0], a[mt][1], a[mt][2], a[mt][3],
                            bb[0], bb[2]);
                    mma_f16(acc[mt][2 * p + 1], a[mt][0], a[mt][1], a[mt][2], a[mt][3],
                            bb[1], bb[3]);
                }
            }
        }
        if (k0 < 15) {
            __half* Ad = As + ((k0 + 1) & 1) * 128 * 72;
            __half* Bd = Bs + ((k0 + 1) & 1) * 128 * 72;
#pragma unroll
            for (int i = 0; i < 4; ++i) {
                int row = r0 + i * 32;
                *(uint4*)&Ad[row * 72 + seg * 8] = ar[i];
                *(uint4*)&Bd[row * 72 + seg * 8] = br[i];
            }
        }
        __syncthreads();
    }

#pragma unroll
    for (int mt = 0; mt < 4; ++mt) {
#pragma unroll
        for (int nt = 0; nt < 4; ++nt) {
            int ncol = n0 + wn + nt * 8 + 2 * t4;
            float bx = __ldg(&bias[ncol]);
            float by = __ldg(&bias[ncol + 1]);
#pragma unroll
            for (int rr = 0; rr < 2; ++rr) {
                int m = m0 + wm + mt * 16 + g + rr * 8;
                float vx = acc[mt][nt][rr * 2] + bx;
                float vy = acc[mt][nt][rr * 2 + 1] + by;
                if (MODE == 0) {
                    int bb2 = m >> 11, ss = m & 2047;
                    int h = ncol / 192;
                    int rem = ncol - h * 192;
                    int part = rem >> 6;
                    int d = rem & 63;
                    if (part == 0) { vx *= SCALE2; vy *= SCALE2; }
                    size_t dst = (((size_t)(bb2 * H_ + h)) * S_ + ss) * HD_ + d;
                    __half* dstp = (part == 0 ? g_Qh : (part == 1 ? g_Kh : g_Vh));
                    __half2 hv = __floats2half2_rn(vx, vy);
                    *(__half2*)&dstp[dst] = hv;
                } else {
                    *(float2*)&out[(size_t)m * D_ + ncol] = make_float2(vx, vy);
                }
            }
        }
    }
}

// ---------------------------------------------------------------------------
// Flash attention, fp16 mma. Issue-minimized: 4-stage cp.async K/V ring
// (1 barrier + 1 wait per 2 tiles), Q fragments register-resident,
// fragment-major mask bias (4 LDG.128/tile), half-domain centering.
// ---------------------------------------------------------------------------
__global__ __launch_bounds__(256, 2) void attn_tc() {
    extern __shared__ __half shh[];
    __half* Qs = shh;                   // [128][72]
    __half* Ks = shh + 128 * 72;        // [4][64][72]
    __half* Vs = Ks + 4 * 64 * 72;      // [4][64][72]

    const int bh = blockIdx.y;
    const int q0 = blockIdx.x * 128;
    const int t = threadIdx.x;
    const int w = t >> 5;
    const int lane = t & 31;
    const int g = lane >> 2;
    const int t4 = lane & 3;

    const size_t base = (size_t)bh * (S_ * HD_);
    const __half* Qg = g_Qh + base;
    const __half* Kg = g_Kh + base;
    const __half* Vg = g_Vh + base;

    const int seg = t & 7;
    const int r0 = t >> 3;

    const unsigned sQ = smem_u32(Qs);
    const unsigned sK = smem_u32(Ks);
    const unsigned sV = smem_u32(Vs);
    const unsigned KBUF = 64 * 72 * 2;
    const unsigned qoff = (w * 16 + (lane & 15)) * 144 + (lane >> 4) * 16;
    const unsigned koff = (lane & 15) * 144 + (lane >> 4) * 16;

    // stage Q
#pragma unroll
    for (int i = 0; i < 4; ++i) {
        int row = r0 + i * 32;
        *(uint4*)&Qs[row * 72 + seg * 8] =
            *(const uint4*)(Qg + (size_t)(q0 + row) * HD_ + seg * 8);
    }
    // cp.async stage K/V tiles 0,1 into ring stages 0,1 (one group per tile)
#pragma unroll
    for (int tile = 0; tile < 2; ++tile) {
#pragma unroll
        for (int i = 0; i < 2; ++i) {
            int row = r0 + i * 32;
            cp16(sK + tile * KBUF + (row * 72 + seg * 8) * 2,
                 Kg + ((size_t)tile * 64 + row) * HD_ + seg * 8);
            cp16(sV + tile * KBUF + (row * 72 + seg * 8) * 2,
                 Vg + ((size_t)tile * 64 + row) * HD_ + seg * 8);
        }
        CP_COMMIT();
    }
    __syncthreads();

    // Q fragments register-resident (loop-invariant)
    unsigned qa[4][4];
#pragma unroll
    for (int ks = 0; ks < 4; ++ks) ldsm4(qa[ks], sQ + qoff + ks * 32);

    const int qrow0 = q0 + w * 16 + g;
    const int qrow1 = qrow0 + 8;
    const unsigned* bq0 = (const unsigned*)(g_Bh + (size_t)qrow0 * S_) + t4 * 8;
    const unsigned* bq1 = (const unsigned*)(g_Bh + (size_t)qrow1 * S_) + t4 * 8;

    float o[8][4];
#pragma unroll
    for (int nt = 0; nt < 8; ++nt)
#pragma unroll
        for (int i = 0; i < 4; ++i) o[nt][i] = 0.0f;
    float m0s = -INFINITY, m1s = -INFINITY, l0 = 0.0f, l1 = 0.0f;

    for (int jj = 0; jj < 32; jj += 2) {
        cp_wait<0>();
        __syncthreads();
        const unsigned ph = (unsigned)(jj & 2);
#pragma unroll
        for (int u = 0; u < 2; ++u) {
            const int j = jj + u;
            const unsigned bK = sK + (ph + u) * KBUF;
            const unsigned bV = sV + (ph + u) * KBUF;
            // prefetch tile j+2 into ring stage (j+2)&3 via cp.async
            if (j + 2 < 32) {
                const __half* Kn = Kg + (size_t)(j + 2) * 64 * HD_;
                const __half* Vn = Vg + (size_t)(j + 2) * 64 * HD_;
                unsigned dK = sK + ((ph + u + 2) & 3) * KBUF;
                unsigned dV = sV + ((ph + u + 2) & 3) * KBUF;
#pragma unroll
                for (int i = 0; i < 2; ++i) {
                    int row = r0 + i * 32;
                    cp16(dK + (row * 72 + seg * 8) * 2, Kn + (size_t)row * HD_ + seg * 8);
                    cp16(dV + (row * 72 + seg * 8) * 2, Vn + (size_t)row * HD_ + seg * 8);
                }
                CP_COMMIT();
            }
            // mask bias (fragment-major): 4 LDG.128
            uint4 ba = __ldg((const uint4*)(bq0 + j * 32));
            uint4 bb4 = __ldg((const uint4*)(bq0 + j * 32 + 4));
            uint4 bc = __ldg((const uint4*)(bq1 + j * 32));
            uint4 bd = __ldg((const uint4*)(bq1 + j * 32 + 4));
            unsigned bw0[8] = {ba.x, ba.y, ba.z, ba.w, bb4.x, bb4.y, bb4.z, bb4.w};
            unsigned bw1[8] = {bc.x, bc.y, bc.z, bc.w, bd.x, bd.y, bd.z, bd.w};

            // S = Q @ K^T
            float sc[8][4];
#pragma unroll
            for (int nt = 0; nt < 8; ++nt)
#pragma unroll
                for (int i = 0; i < 4; ++i) sc[nt][i] = 0.0f;
#pragma unroll
            for (int ks = 0; ks < 4; ++ks) {
#pragma unroll
                for (int p = 0; p < 4; ++p) {
                    unsigned kb[4];
                    ldsm4(kb, bK + koff + p * 16 * 144 + ks * 32);
                    mma_f16(sc[2 * p], qa[ks][0], qa[ks][1], qa[ks][2], qa[ks][3],
                            kb[0], kb[2]);
                    mma_f16(sc[2 * p + 1], qa[ks][0], qa[ks][1], qa[ks][2], qa[ks][3],
                            kb[1], kb[3]);
                }
            }

            // running max over unmasked logits
            float mx0 = -INFINITY, mx1 = -INFINITY;
#pragma unroll
            for (int nt = 0; nt < 8; ++nt) {
                mx0 = fmaxf(mx0, fmaxf(sc[nt][0], sc[nt][1]));
                mx1 = fmaxf(mx1, fmaxf(sc[nt][2], sc[nt][3]));
            }
            mx0 = fmaxf(mx0, __shfl_xor_sync(0xffffffffu, mx0, 1));
            mx0 = fmaxf(mx0, __shfl_xor_sync(0xffffffffu, mx0, 2));
            mx1 = fmaxf(mx1, __shfl_xor_sync(0xffffffffu, mx1, 1));
            mx1 = fmaxf(mx1, __shfl_xor_sync(0xffffffffu, mx1, 2));
            float mn0 = fmaxf(m0s, mx0), mn1 = fmaxf(m1s, mx1);
            float al0 = ex2(m0s - mn0), al1 = ex2(m1s - mn1);
            m0s = mn0; m1s = mn1;
#pragma unroll
            for (int nt = 0; nt < 8; ++nt) {
                o[nt][0] *= al0; o[nt][1] *= al0;
                o[nt][2] *= al1; o[nt][3] *= al1;
            }

            // pack -> +(-mn) -> +bias -> exp, all in half2 domain
            unsigned mneg0 = h2(-mn0, -mn0);
            unsigned mneg1 = h2(-mn1, -mn1);
            unsigned ph_lo[8], ph_hi[8];
#pragma unroll
            for (int nt = 0; nt < 8; ++nt) {
                ph_lo[nt] = ex2h2(hadd2u(hadd2u(h2(sc[nt][0], sc[nt][1]), mneg0), bw0[nt]));
                ph_hi[nt] = ex2h2(hadd2u(hadd2u(h2(sc[nt][2], sc[nt][3]), mneg1), bw1[nt]));
            }

            // row sums via ones-matrix mma
            float rs[4] = {0.0f, 0.0f, 0.0f, 0.0f};
#pragma unroll
            for (int kt = 0; kt < 4; ++kt)
                mma_f16(rs, ph_lo[2 * kt], ph_hi[2 * kt], ph_lo[2 * kt + 1],
                        ph_hi[2 * kt + 1], ONESH2, ONESH2);
            l0 = al0 * l0 + rs[0];
            l1 = al1 * l1 + rs[2];

            // O += P @ V
#pragma unroll
            for (int kt = 0; kt < 4; ++kt) {
                unsigned a0 = ph_lo[2 * kt];
                unsigned a1 = ph_hi[2 * kt];
                unsigned a2 = ph_lo[2 * kt + 1];
                unsigned a3 = ph_hi[2 * kt + 1];
#pragma unroll
                for (int q = 0; q < 4; ++q) {
                    unsigned vb[4];
                    ldsm4t(vb, bV + koff + kt * 16 * 144 + q * 32);
                    mma_f16(o[2 * q], a0, a1, a2, a3, vb[0], vb[1]);
                    mma_f16(o[2 * q + 1], a0, a1, a2, a3, vb[2], vb[3]);
                }
            }
        }
    }

    // epilogue
    const int bb = bh >> 4;
    const int h = bh & 15;
    float inv0 = 1.0f / l0, inv1 = 1.0f / l1;
#pragma unroll
    for (int nt = 0; nt < 8; ++nt) {
        int dcol = h * 64 + nt * 8 + 2 * t4;
        size_t rr0 = ((size_t)bb * S_ + qrow0) * D_ + dcol;
        size_t rr1 = ((size_t)bb * S_ + qrow1) * D_ + dcol;
        __half2 v0 = __floats2half2_rn(o[nt][0] * inv0, o[nt][1] * inv0);
        __half2 v1 = __floats2half2_rn(o[nt][2] * inv1, o[nt][3] * inv1);
        *(__half2*)&g_Ch[rr0] = v0;
        *(__half2*)&g_Ch[rr1] = v1;
    }
}

// ---------------------------------------------------------------------------
extern "C" void kernel_launch(void* const* d_in, const int* in_sizes, int n_in,
                              void* d_out, int out_size) {
    const float* x     = (const float*)d_in[0];
    const int*   mask  = (const int*)d_in[1];
    const float* w_qkv = (const float*)d_in[2];
    const float* b_qkv = (const float*)d_in[3];
    const float* w_o   = (const float*)d_in[4];
    const float* b_o   = (const float*)d_in[5];
    float* out = (float*)d_out;

    const int gemm_smem = 4 * 128 * 72 * 2;              // 73728
    const int attn_smem = (128 * 72 + 8 * 64 * 72) * 2;  // 92160

    cudaFuncSetAttribute(gemm_tc<0>, cudaFuncAttributeMaxDynamicSharedMemorySize, gemm_smem);
    cudaFuncSetAttribute(gemm_tc<1>, cudaFuncAttributeMaxDynamicSharedMemorySize, gemm_smem);
    cudaFuncSetAttribute(attn_tc, cudaFuncAttributeMaxDynamicSharedMemorySize, attn_smem);

    // 0) one-time prep
    biasprep<<<(S_ * S_ / 2) / (4 * 256), 256>>>(mask);   // 2048 blocks
    __half *dXh, *dW1h, *dW2h, *dCh;
    cudaGetSymbolAddress((void**)&dXh, g_Xh);
    cudaGetSymbolAddress((void**)&dW1h, g_W1h);
    cudaGetSymbolAddress((void**)&dW2h, g_W2h);
    cudaGetSymbolAddress((void**)&dCh, g_Ch);
    conv_all<<<4096, 256>>>(x, w_qkv, w_o);

    // 1) QKV projection
    gemm_tc<0><<<dim3(3072 / 128, 4096 / 128), 256, gemm_smem>>>(dXh, dW1h, b_qkv, nullptr);

    // 2) flash attention
    attn_tc<<<dim3(S_ / 128, B_ * H_), 256, attn_smem>>>();

    // 3) output projection
    gemm_tc<1><<<dim3(1024 / 128, 4096 / 128), 256, gemm_smem>>>(dCh, dW2h, b_o, out);
}